// round 8
// baseline (speedup 1.0000x reference)
#include <cuda_runtime.h>
#include <cuda_bf16.h>
#include <math.h>
#include <stdint.h>

#define BB 4
#define NN 256
#define TT 64
#define DD 128
#define DR 32
#define DH 128
#define WF_LD (3*DD+DR)   // 416

// ---------------- device scratch ----------------
__device__ float g_A   [(size_t)BB*NN*TT*DD];   // (b,n,t,e)
__device__ float g_S   [(size_t)BB*TT*NN*NN];   // (b,t,i,j) scores
__device__ float g_Z2  [(size_t)BB*TT*NN*DD];   // (b,t,i,e)
__device__ float g_P   [BB*NN*TT*DR];   // (b,i,t,r)
__device__ float g_qbr [BB*NN*TT];
__device__ float g_wsum[BB*NN*TT];      // (b,i,t)
__device__ float g_WR  [BB*NN*TT*DR];   // (b,i,t,r)
__device__ float g_Ej  [BB*NN*DD];      // (b,j,e)
__device__ float g_dsum[BB*NN*DD];
__device__ float g_W4t [DD*DD];         // [dd][e]
__device__ float g_WQR [DD*DR];
__device__ float g_brq [DR];
__device__ float g_wqbr[DD];
__device__ float g_c0;

// bf16 split operands
__device__ __nv_bfloat16 g_Hh [(size_t)BB*NN*TT*DD];
__device__ __nv_bfloat16 g_Hl [(size_t)BB*NN*TT*DD];
__device__ __nv_bfloat16 g_Wch[4*DH*DD];
__device__ __nv_bfloat16 g_Wcl[4*DH*DD];
__device__ __nv_bfloat16 g_qh [(size_t)BB*TT*NN*DH];
__device__ __nv_bfloat16 g_ql [(size_t)BB*TT*NN*DH];
__device__ __nv_bfloat16 g_kh [(size_t)BB*TT*NN*DH];
__device__ __nv_bfloat16 g_kl [(size_t)BB*TT*NN*DH];
__device__ __nv_bfloat16 g_Bph[(size_t)BB*TT*NN*DD];
__device__ __nv_bfloat16 g_Bpl[(size_t)BB*TT*NN*DD];
__device__ __nv_bfloat16 g_wh [(size_t)BB*TT*NN*NN];
__device__ __nv_bfloat16 g_wl [(size_t)BB*TT*NN*NN];

// ---------------- helpers ----------------
__device__ __forceinline__ void split2(float x, __nv_bfloat16* ph, __nv_bfloat16* pl) {
    __nv_bfloat16 h = __float2bfloat16(x);
    *ph = h;
    *pl = __float2bfloat16(x - __bfloat162float(h));
}
__device__ __forceinline__ uint32_t smem_u32p(const void* p) {
    return (uint32_t)__cvta_generic_to_shared(p);
}
__device__ __forceinline__ void ldsm4(uint32_t& r0, uint32_t& r1, uint32_t& r2, uint32_t& r3, uint32_t a) {
    asm volatile("ldmatrix.sync.aligned.m8n8.x4.shared.b16 {%0,%1,%2,%3}, [%4];"
                 : "=r"(r0), "=r"(r1), "=r"(r2), "=r"(r3) : "r"(a));
}
__device__ __forceinline__ void ldsm4t(uint32_t& r0, uint32_t& r1, uint32_t& r2, uint32_t& r3, uint32_t a) {
    asm volatile("ldmatrix.sync.aligned.m8n8.x4.trans.shared.b16 {%0,%1,%2,%3}, [%4];"
                 : "=r"(r0), "=r"(r1), "=r"(r2), "=r"(r3) : "r"(a));
}
__device__ __forceinline__ void mma16816(float* c, const uint32_t* a, const uint32_t* b) {
    asm volatile("mma.sync.aligned.m16n8k16.row.col.f32.bf16.bf16.f32 "
                 "{%0,%1,%2,%3},{%4,%5,%6,%7},{%8,%9},{%0,%1,%2,%3};"
                 : "+f"(c[0]), "+f"(c[1]), "+f"(c[2]), "+f"(c[3])
                 : "r"(a[0]), "r"(a[1]), "r"(a[2]), "r"(a[3]), "r"(b[0]), "r"(b[1]));
}

// ---------------- kprep: fold Wq into Wr path ----------------
__global__ void kprep(const float* __restrict__ Wq, const float* __restrict__ bq,
                      const float* __restrict__ Wr, const float* __restrict__ br) {
    int d = threadIdx.x; // 128
    float acc[DR];
    #pragma unroll
    for (int r = 0; r < DR; r++) acc[r] = 0.f;
    float wq_br = 0.f;
    for (int h = 0; h < DH; h++) {
        float a = Wq[h*DD + d];
        wq_br += a * br[h];
        #pragma unroll
        for (int r = 0; r < DR; r++) acc[r] += a * Wr[h*DR + r];
    }
    #pragma unroll
    for (int r = 0; r < DR; r++) g_WQR[d*DR + r] = acc[r];
    g_wqbr[d] = wq_br;
    if (d < DR) {
        float s = 0.f;
        for (int h = 0; h < DH; h++) s += bq[h] * Wr[h*DR + d];
        g_brq[d] = s;
    }
    if (d == 0) {
        float s = 0.f;
        for (int h = 0; h < DH; h++) s += bq[h] * br[h];
        g_c0 = s;
    }
}

// ---------------- kw: build concatenated weights + transposed W4 ----------------
__global__ void kw_build(const float* __restrict__ Wq, const float* __restrict__ Wk,
                         const float* __restrict__ Wf) {
    int idx = blockIdx.x*blockDim.x + threadIdx.x;
    if (idx >= 4*DH*DD) return;
    int r = idx / DD, c = idx - r*DD;
    float v;
    if      (r < DH)   v = Wq[r*DD + c];
    else if (r < 2*DH) v = Wk[(r-DH)*DD + c];
    else if (r < 3*DH) v = Wf[(r-2*DH)*WF_LD + c];          // W1
    else               v = Wf[(r-3*DH)*WF_LD + DD + c];     // W2
    split2(v, &g_Wch[idx], &g_Wcl[idx]);
}

__global__ void kw4t(const float* __restrict__ Wf) {
    int f = blockIdx.x*256 + threadIdx.x;   // 16384
    int e = f >> 7, dd = f & 127;
    g_W4t[dd*DD + e] = Wf[e*WF_LD + 2*DD + DR + dd];
}

// ---------------- kconv_H: H fp32 -> bf16 hi/lo (float4) ----------------
__global__ void kconv_H(const float* __restrict__ H) {
    int i = blockIdx.x*blockDim.x + threadIdx.x;   // float4 index
    float4 x = ((const float4*)H)[i];
    __nv_bfloat16 h0,l0,h1,l1,h2,l2,h3,l3;
    split2(x.x,&h0,&l0); split2(x.y,&h1,&l1); split2(x.z,&h2,&l2); split2(x.w,&h3,&l3);
    __nv_bfloat162* ph = (__nv_bfloat162*)g_Hh;
    __nv_bfloat162* pl = (__nv_bfloat162*)g_Hl;
    ph[i*2]   = __nv_bfloat162{h0,h1};
    ph[i*2+1] = __nv_bfloat162{h2,h3};
    pl[i*2]   = __nv_bfloat162{l0,l1};
    pl[i*2+1] = __nv_bfloat162{l2,l3};
}

// ---------------- k0a: dsum[b,j,d] = sum_t dH[b,j,t,d] ----------------
__global__ __launch_bounds__(256) void k0a(const float* __restrict__ dH) {
    int bj = blockIdx.x;
    int tid = threadIdx.x;
    int d4 = tid & 31;     // float4 lane (128 d / 4)
    int ts = tid >> 5;     // 0..7
    const float4* p = (const float4*)(dH + (size_t)bj*TT*DD) + d4;
    float4 s = make_float4(0.f,0.f,0.f,0.f);
    #pragma unroll
    for (int t = ts; t < TT; t += 8) {
        float4 v = p[t*32];
        s.x += v.x; s.y += v.y; s.z += v.z; s.w += v.w;
    }
    __shared__ float4 red[8][32];
    red[ts][d4] = s;
    __syncthreads();
    if (ts == 0) {
        float4 a = red[0][d4];
        #pragma unroll
        for (int k = 1; k < 8; k++) {
            float4 b = red[k][d4];
            a.x += b.x; a.y += b.y; a.z += b.z; a.w += b.w;
        }
        ((float4*)(g_dsum + (size_t)bj*DD))[d4] = a;
    }
}

// ---------------- k0b: Ej = dsum @ W4^T (via W4t) ----------------
__global__ __launch_bounds__(256) void k0b() {
    int r0 = blockIdx.x * 16;   // 64 blocks, 16 rows each
    __shared__ float ds[16][DD];
    int tid = threadIdx.x;
    #pragma unroll
    for (int l = 0; l < 8; l++) {
        int f = l*256 + tid;
        ds[f >> 7][f & 127] = g_dsum[(size_t)(r0 + (f >> 7))*DD + (f & 127)];
    }
    __syncthreads();
    int e = tid & 127, rh = tid >> 7;
    float acc[8];
    #pragma unroll
    for (int rr = 0; rr < 8; rr++) acc[rr] = 0.f;
    for (int dd = 0; dd < DD; dd++) {
        float wv = g_W4t[dd*DD + e];
        #pragma unroll
        for (int rr = 0; rr < 8; rr++) acc[rr] += ds[rh*8 + rr][dd]*wv;
    }
    #pragma unroll
    for (int rr = 0; rr < 8; rr++)
        g_Ej[(size_t)(r0 + rh*8 + rr)*DD + e] = acc[rr];
}

// ---------------- k1m: fused projection GEMM (tensor cores, reordered passes) ----------------
__global__ __launch_bounds__(256) void k1m(const float* __restrict__ bq,
                                           const float* __restrict__ bk) {
    __shared__ __align__(16) __nv_bfloat16 As[128][72];
    __shared__ __align__(16) __nv_bfloat16 Bs[128][72];
    __shared__ float biasq[DH], biask[DH];
    int tid = threadIdx.x, lane = tid & 31, w = tid >> 5;
    int wm = w & 1, wn = w >> 1;
    if (tid < DH) { biasq[tid] = bq[tid]; biask[tid] = bk[tid]; }
    const int n0 = blockIdx.x * 128;
    const int m0 = blockIdx.y * 128;
    float acc[4][4][4];
    #pragma unroll
    for (int i = 0; i < 4; i++)
        #pragma unroll
        for (int j = 0; j < 4; j++)
            #pragma unroll
            for (int r = 0; r < 4; r++) acc[i][j][r] = 0.f;
    uint32_t asb = smem_u32p(&As[0][0]);
    uint32_t bsb = smem_u32p(&Bs[0][0]);
    const uint32_t* Ah32 = (const uint32_t*)g_Hh;
    const uint32_t* Al32 = (const uint32_t*)g_Hl;
    const uint32_t* Bh32 = (const uint32_t*)g_Wch;
    const uint32_t* Bl32 = (const uint32_t*)g_Wcl;

    auto loadA = [&](const uint32_t* src, int kc) {
        #pragma unroll
        for (int l = 0; l < 16; l++) {
            int f = l*256 + tid; int r = f >> 5, cu = f & 31;
            ((uint32_t*)As)[r*36 + cu] = src[(size_t)(m0 + r)*64 + kc*32 + cu];
        }
    };
    auto loadB = [&](const uint32_t* src, int kc) {
        #pragma unroll
        for (int l = 0; l < 16; l++) {
            int f = l*256 + tid; int r = f >> 5, cu = f & 31;
            ((uint32_t*)Bs)[r*36 + cu] = src[(size_t)(n0 + r)*64 + kc*32 + cu];
        }
    };
    auto mmaTile = [&]() {
        #pragma unroll
        for (int ki = 0; ki < 4; ki++) {
            uint32_t a[4][4], b[4][2];
            #pragma unroll
            for (int mf = 0; mf < 4; mf++)
                ldsm4(a[mf][0], a[mf][1], a[mf][2], a[mf][3],
                      asb + ((wm*64 + mf*16 + (lane & 15))*72 + ki*16 + (lane >> 4)*8)*2);
            #pragma unroll
            for (int g = 0; g < 2; g++) {
                uint32_t r0, r1, r2, r3;
                ldsm4(r0, r1, r2, r3,
                      bsb + ((wn*32 + g*16 + (lane & 15))*72 + ki*16 + (lane >> 4)*8)*2);
                b[g*2][0] = r0; b[g*2][1] = r2; b[g*2+1][0] = r1; b[g*2+1][1] = r3;
            }
            #pragma unroll
            for (int mf = 0; mf < 4; mf++)
                #pragma unroll
                for (int nf = 0; nf < 4; nf++) mma16816(acc[mf][nf], a[mf], b[nf]);
        }
    };

    #pragma unroll 1
    for (int kc = 0; kc < 2; kc++) {
        loadA(Al32, kc); loadB(Bh32, kc); __syncthreads();
        mmaTile(); __syncthreads();        // lo·hi
        loadA(Ah32, kc); __syncthreads();
        mmaTile(); __syncthreads();        // hi·hi
        loadB(Bl32, kc); __syncthreads();
        mmaTile(); __syncthreads();        // hi·lo
    }
    // epilogue
    int seg = blockIdx.x;  // 0:q 1:k 2:A 3:Bp
    #pragma unroll
    for (int mf = 0; mf < 4; mf++)
        #pragma unroll
        for (int nf = 0; nf < 4; nf++)
            #pragma unroll
            for (int r = 0; r < 4; r++) {
                int m = m0 + wm*64 + mf*16 + (lane >> 2) + ((r >> 1) << 3);
                int nl = wn*32 + nf*8 + ((lane & 3) << 1) + (r & 1);
                float v = acc[mf][nf][r];
                int b_ = m >> 14, nn = (m >> 6) & 255, t = m & 63;
                size_t base = (size_t)((b_*TT + t)*NN + nn);
                if (seg == 0) {
                    size_t d = base*DH + nl;
                    split2(v + biasq[nl], g_qh + d, g_ql + d);
                } else if (seg == 1) {
                    size_t d = base*DH + nl;
                    split2(v + biask[nl], g_kh + d, g_kl + d);
                } else if (seg == 2) {
                    g_A[(size_t)m*DD + nl] = v;
                } else {
                    float bpv = v + g_Ej[(size_t)(b_*NN + nn)*DD + nl];
                    size_t d = base*DD + nl;
                    split2(bpv, g_Bph + d, g_Bpl + d);
                }
            }
}

// ---------------- k2m: scores per (b,t): Q @ K^T ----------------
__global__ __launch_bounds__(256) void k2m() {
    __shared__ __align__(16) __nv_bfloat16 As[128][72];
    __shared__ __align__(16) __nv_bfloat16 Bs[128][72];
    int tid = threadIdx.x, lane = tid & 31, w = tid >> 5;
    int wm = w & 1, wn = w >> 1;
    int bt = blockIdx.z;
    const int n0 = blockIdx.x * 128;
    const int m0 = blockIdx.y * 128;
    float acc[4][4][4];
    #pragma unroll
    for (int i = 0; i < 4; i++)
        #pragma unroll
        for (int j = 0; j < 4; j++)
            #pragma unroll
            for (int r = 0; r < 4; r++) acc[i][j][r] = 0.f;
    uint32_t asb = smem_u32p(&As[0][0]);
    uint32_t bsb = smem_u32p(&Bs[0][0]);
    const uint32_t* qh32 = (const uint32_t*)g_qh + (size_t)bt*NN*64;
    const uint32_t* ql32 = (const uint32_t*)g_ql + (size_t)bt*NN*64;
    const uint32_t* kh32 = (const uint32_t*)g_kh + (size_t)bt*NN*64;
    const uint32_t* kl32 = (const uint32_t*)g_kl + (size_t)bt*NN*64;

    auto loadA = [&](const uint32_t* src, int kc) {
        #pragma unroll
        for (int l = 0; l < 16; l++) {
            int f = l*256 + tid; int r = f >> 5, cu = f & 31;
            ((uint32_t*)As)[r*36 + cu] = src[(size_t)(m0 + r)*64 + kc*32 + cu];
        }
    };
    auto loadB = [&](const uint32_t* src, int kc) {
        #pragma unroll
        for (int l = 0; l < 16; l++) {
            int f = l*256 + tid; int r = f >> 5, cu = f & 31;
            ((uint32_t*)Bs)[r*36 + cu] = src[(size_t)(n0 + r)*64 + kc*32 + cu];
        }
    };
    auto mmaTile = [&]() {
        #pragma unroll
        for (int ki = 0; ki < 4; ki++) {
            uint32_t a[4][4], b[4][2];
            #pragma unroll
            for (int mf = 0; mf < 4; mf++)
                ldsm4(a[mf][0], a[mf][1], a[mf][2], a[mf][3],
                      asb + ((wm*64 + mf*16 + (lane & 15))*72 + ki*16 + (lane >> 4)*8)*2);
            #pragma unroll
            for (int g = 0; g < 2; g++) {
                uint32_t r0, r1, r2, r3;
                ldsm4(r0, r1, r2, r3,
                      bsb + ((wn*32 + g*16 + (lane & 15))*72 + ki*16 + (lane >> 4)*8)*2);
                b[g*2][0] = r0; b[g*2][1] = r2; b[g*2+1][0] = r1; b[g*2+1][1] = r3;
            }
            #pragma unroll
            for (int mf = 0; mf < 4; mf++)
                #pragma unroll
                for (int nf = 0; nf < 4; nf++) mma16816(acc[mf][nf], a[mf], b[nf]);
        }
    };

    #pragma unroll 1
    for (int kc = 0; kc < 2; kc++) {
        loadA(ql32, kc); loadB(kh32, kc); __syncthreads();
        mmaTile(); __syncthreads();
        loadA(qh32, kc); __syncthreads();
        mmaTile(); __syncthreads();
        loadB(kl32, kc); __syncthreads();
        mmaTile(); __syncthreads();
    }
    float* C = g_S + (size_t)bt*NN*NN;
    #pragma unroll
    for (int mf = 0; mf < 4; mf++)
        #pragma unroll
        for (int nf = 0; nf < 4; nf++) {
            int m = m0 + wm*64 + mf*16 + (lane >> 2);
            int n = n0 + wn*32 + nf*8 + ((lane & 3) << 1);
            float2 v0 = make_float2(acc[mf][nf][0], acc[mf][nf][1]);
            float2 v1 = make_float2(acc[mf][nf][2], acc[mf][nf][3]);
            *(float2*)&C[(size_t)m*NN + n] = v0;
            *(float2*)&C[(size_t)(m + 8)*NN + n] = v1;
        }
}

// ---------------- ksoft: add R-term, softmax over t, mask, wsum, write w (bf16 split only) ----------------
__global__ __launch_bounds__(256) void ksoft(const float* __restrict__ R) {
    int bi = blockIdx.x; int b = bi >> 8, i = bi & 255;
    int j = threadIdx.x;
    __shared__ float Ps[TT][DR];
    __shared__ float qbrs[TT];
    __shared__ float ws[TT];
    #pragma unroll
    for (int l = 0; l < 8; l++) {
        int f = l*256 + j; int t = f >> 5, r = f & 31;
        Ps[t][r] = g_P[((size_t)bi*TT + t)*DR + r];
    }
    if (j < TT) { qbrs[j] = g_qbr[(size_t)bi*TT + j]; ws[j] = 0.f; }
    __syncthreads();
    float Rr[DR];
    const float* Rp = R + ((size_t)bi*NN + j)*DR;
    #pragma unroll
    for (int r4 = 0; r4 < 8; r4++) {
        float4 v = *(const float4*)(Rp + r4*4);
        Rr[r4*4+0] = v.x; Rr[r4*4+1] = v.y; Rr[r4*4+2] = v.z; Rr[r4*4+3] = v.w;
    }
    float sv[TT];
    const float rs = 0.08838834764831845f;  // 1/sqrt(128)
    size_t sbase = ((size_t)b*TT*NN + i)*NN + j;
    #pragma unroll
    for (int t = 0; t < TT; t++) {
        float qk = g_S[sbase + (size_t)t*NN*NN];
        float rt = 0.f;
        #pragma unroll
        for (int r = 0; r < DR; r++) rt += Ps[t][r]*Rr[r];
        sv[t] = (qk + rt + qbrs[t])*rs;
    }
    float mx = sv[0];
    #pragma unroll
    for (int t = 1; t < TT; t++) mx = fmaxf(mx, sv[t]);
    float sum = 0.f;
    #pragma unroll
    for (int t = 0; t < TT; t++) { sv[t] = __expf(sv[t]-mx); sum += sv[t]; }
    float inv = (j == i) ? 0.f : (1.f/sum);
    int lane = j & 31;
    #pragma unroll
    for (int t = 0; t < TT; t++) {
        float wv = sv[t]*inv;
        size_t idx = sbase + (size_t)t*NN*NN;
        split2(wv, g_wh + idx, g_wl + idx);
        float red = wv;
        #pragma unroll
        for (int o = 16; o; o >>= 1) red += __shfl_xor_sync(0xffffffffu, red, o);
        if (lane == 0) atomicAdd(&ws[t], red);
    }
    __syncthreads();
    if (j < TT) g_wsum[(size_t)bi*TT + j] = ws[j];
}

// ---------------- kp: P = H @ WQR + brq ; qbr = H @ wqbr + c0 ----------------
__global__ __launch_bounds__(256) void kp_P(const float* __restrict__ H) {
    int bi = blockIdx.x;
    __shared__ float Hs[TT][33];
    __shared__ float Ws[32][DR];
    __shared__ float wqbrs[32];
    int tid = threadIdx.x;
    int t = tid >> 2, rg = (tid & 3)*8;
    float acc[8];
    #pragma unroll
    for (int r = 0; r < 8; r++) acc[r] = 0.f;
    float qacc = 0.f;
    const float* Hbase = H + (size_t)bi*TT*DD;
    for (int d0 = 0; d0 < DD; d0 += 32) {
        #pragma unroll
        for (int l = 0; l < 8; l++) {
            int f = l*256 + tid; int t2 = f >> 5, dd = f & 31;
            Hs[t2][dd] = Hbase[t2*DD + d0 + dd];
        }
        #pragma unroll
        for (int l = 0; l < 4; l++) {
            int f = l*256 + tid; int dd = f >> 5, r = f & 31;
            Ws[dd][r] = g_WQR[(d0 + dd)*DR + r];
        }
        if (tid < 32) wqbrs[tid] = g_wqbr[d0 + tid];
        __syncthreads();
        #pragma unroll
        for (int dd = 0; dd < 32; dd++) {
            float a = Hs[t][dd];
            #pragma unroll
            for (int rr = 0; rr < 8; rr++) acc[rr] += a * Ws[dd][rg + rr];
            qacc += a * wqbrs[dd];
        }
        __syncthreads();
    }
    size_t pb = ((size_t)bi*TT + t)*DR + rg;
    #pragma unroll
    for (int rr = 0; rr < 8; rr++) g_P[pb + rr] = acc[rr] + g_brq[rg + rr];
    if (rg == 0) g_qbr[(size_t)bi*TT + t] = qacc + g_c0;
}

// ---------------- kwr: WR[b,i,t,r] = sum_j w[b,t,i,j] * R[b,i,j,r] (w = wh+wl) ----------------
__global__ __launch_bounds__(256) void kwr(const float* __restrict__ R) {
    int bi = blockIdx.x; int b = bi >> 8, i = bi & 255;
    __shared__ float Rs[32][33];
    __shared__ float wsm[TT][33];
    int tid = threadIdx.x;
    int t = tid >> 2, rg = (tid & 3)*8;
    float acc[8];
    #pragma unroll
    for (int r = 0; r < 8; r++) acc[r] = 0.f;
    for (int j0 = 0; j0 < NN; j0 += 32) {
        #pragma unroll
        for (int l = 0; l < 4; l++) {
            int f = l*256 + tid; int jj = f >> 5, r = f & 31;
            Rs[jj][r] = R[((size_t)bi*NN + j0 + jj)*DR + r];
        }
        #pragma unroll
        for (int l = 0; l < 8; l++) {
            int f = l*256 + tid; int t2 = f >> 5, jj = f & 31;
            size_t idx = ((size_t)(b*TT + t2)*NN + i)*NN + j0 + jj;
            wsm[t2][jj] = __bfloat162float(g_wh[idx]) + __bfloat162float(g_wl[idx]);
        }
        __syncthreads();
        #pragma unroll
        for (int jj = 0; jj < 32; jj++) {
            float wv = wsm[t][jj];
            #pragma unroll
            for (int rr = 0; rr < 8; rr++) acc[rr] += wv * Rs[jj][rg + rr];
        }
        __syncthreads();
    }
    size_t ob = ((size_t)bi*TT + t)*DR + rg;
    #pragma unroll
    for (int rr = 0; rr < 8; rr++) g_WR[ob + rr] = acc[rr];
}

// ---------------- k3m: z2 per (b,t): w @ Bp ----------------
__global__ __launch_bounds__(256) void k3m() {
    __shared__ __align__(16) __nv_bfloat16 As[128][72];   // w tile: 128 i x 64 j
    __shared__ __align__(16) __nv_bfloat16 Bs[64][136];   // Bp tile: 64 j x 128 e
    int tid = threadIdx.x, lane = tid & 31, w = tid >> 5;
    int wm = w & 1, wn = w >> 1;
    int bt = blockIdx.z;
    const int m0 = blockIdx.y * 128;
    float acc[4][4][4];
    #pragma unroll
    for (int i = 0; i < 4; i++)
        #pragma unroll
        for (int j = 0; j < 4; j++)
            #pragma unroll
            for (int r = 0; r < 4; r++) acc[i][j][r] = 0.f;
    uint32_t asb = smem_u32p(&As[0][0]);
    uint32_t bsb = smem_u32p(&Bs[0][0]);
    const uint32_t* wh32  = (const uint32_t*)g_wh  + (size_t)bt*NN*(NN/2);
    const uint32_t* wl32  = (const uint32_t*)g_wl  + (size_t)bt*NN*(NN/2);
    const uint32_t* bph32 = (const uint32_t*)g_Bph + (size_t)bt*NN*(DD/2);
    const uint32_t* bpl32 = (const uint32_t*)g_Bpl + (size_t)bt*NN*(DD/2);

    auto loadA = [&](const uint32_t* src, int kc) {
        #pragma unroll
        for (int l = 0; l < 16; l++) {
            int f = l*256 + tid; int r = f >> 5, cu = f & 31;
            ((uint32_t*)As)[r*36 + cu] = src[(size_t)(m0 + r)*128 + kc*32 + cu];
        }
    };
    auto loadB = [&](const uint32_t* src, int kc) {
        #pragma unroll
        for (int l = 0; l < 16; l++) {
            int f = l*256 + tid; int r = f >> 6, cu = f & 63;
            ((uint32_t*)Bs)[r*68 + cu] = src[(size_t)(kc*64 + r)*64 + cu];
        }
    };
    auto mmaTile = [&]() {
        #pragma unroll
        for (int ki = 0; ki < 4; ki++) {
            uint32_t a[4][4], b[4][2];
            #pragma unroll
            for (int mf = 0; mf < 4; mf++)
                ldsm4(a[mf][0], a[mf][1], a[mf][2], a[mf][3],
                      asb + ((wm*64 + mf*16 + (lane & 15))*72 + ki*16 + (lane >> 4)*8)*2);
            #pragma unroll
            for (int g = 0; g < 2; g++) {
                uint32_t r0, r1, r2, r3;
                ldsm4t(r0, r1, r2, r3,
                       bsb + ((ki*16 + (lane & 15))*136 + wn*32 + g*16 + (lane >> 4)*8)*2);
                b[g*2][0] = r0; b[g*2][1] = r1; b[g*2+1][0] = r2; b[g*2+1][1] = r3;
            }
            #pragma unroll
            for (int mf = 0; mf < 4; mf++)
                #pragma unroll
                for (int nf = 0; nf < 4; nf++) mma16816(acc[mf][nf], a[mf], b[nf]);
        }
    };

    #pragma unroll 1
    for (int kc = 0; kc < 4; kc++) {
        loadA(wl32, kc); loadB(bph32, kc); __syncthreads();
        mmaTile(); __syncthreads();
        loadA(wh32, kc); __syncthreads();
        mmaTile(); __syncthreads();
        loadB(bpl32, kc); __syncthreads();
        mmaTile(); __syncthreads();
    }
    float* C = g_Z2 + (size_t)bt*NN*DD;
    #pragma unroll
    for (int mf = 0; mf < 4; mf++)
        #pragma unroll
        for (int nf = 0; nf < 4; nf++) {
            int m = m0 + wm*64 + mf*16 + (lane >> 2);
            int n = wn*32 + nf*8 + ((lane & 3) << 1);
            float2 v0 = make_float2(acc[mf][nf][0], acc[mf][nf][1]);
            float2 v1 = make_float2(acc[mf][nf][2], acc[mf][nf][3]);
            *(float2*)&C[(size_t)m*DD + n] = v0;
            *(float2*)&C[(size_t)(m + 8)*DD + n] = v1;
        }
}

// ---------------- kfin: warp-per-row z assembly + residual + LayerNorm ----------------
__global__ __launch_bounds__(256) void kfin(const float* __restrict__ H,
                                            const float* __restrict__ Wf,
                                            const float* __restrict__ bf,
                                            const float* __restrict__ gamma,
                                            const float* __restrict__ beta,
                                            float* __restrict__ out) {
    int bi = blockIdx.x; int b = bi >> 8, i = bi & 255;
    __shared__ float W3s[DD][33];
    __shared__ float WRs[TT][DR];
    __shared__ float wsums[TT];
    __shared__ float bfs[DD], gs[DD], bts[DD];
    int tid = threadIdx.x;
    #pragma unroll
    for (int l = 0; l < 16; l++) {
        int f = l*256 + tid; int e = f >> 5, r = f & 31;
        W3s[e][r] = Wf[e*WF_LD + 2*DD + r];
    }
    #pragma unroll
    for (int l = 0; l < 8; l++) {
        int f = l*256 + tid; int t = f >> 5, r = f & 31;
        WRs[t][r] = g_WR[((size_t)bi*TT + t)*DR + r];
    }
    if (tid < TT) wsums[tid] = g_wsum[(size_t)bi*TT + tid];
    if (tid < DD) { bfs[tid] = bf[tid]; gs[tid] = gamma[tid]; bts[tid] = beta[tid]; }
    __syncthreads();
    int lane = tid & 31, w = tid >> 5;
    #pragma unroll 1
    for (int pass = 0; pass < 8; pass++) {
        int t = pass*8 + w;
        size_t rowH = ((size_t)bi*TT + t)*DD;
        size_t rowZ = ((size_t)(b*TT + t)*NN + i)*DD;
        float wst = wsums[t];
        float z3[4];
        #pragma unroll
        for (int k = 0; k < 4; k++) z3[k] = 0.f;
        #pragma unroll
        for (int r = 0; r < DR; r++) {
            float wr = WRs[t][r];
            #pragma unroll
            for (int k = 0; k < 4; k++) z3[k] += wr * W3s[lane + 32*k][r];
        }
        float v[4], s1 = 0.f, s2 = 0.f;
        #pragma unroll
        for (int k = 0; k < 4; k++) {
            int e = lane + 32*k;
            float x = H[rowH + e] + (g_A[rowH + e] + bfs[e])*wst + g_Z2[rowZ + e] + z3[k];
            v[k] = x; s1 += x; s2 += x*x;
        }
        #pragma unroll
        for (int o = 16; o; o >>= 1) {
            s1 += __shfl_xor_sync(0xffffffffu, s1, o);
            s2 += __shfl_xor_sync(0xffffffffu, s2, o);
        }
        float mu = s1*(1.f/128.f);
        float var = s2*(1.f/128.f) - mu*mu;
        float isd = rsqrtf(var + 1e-5f);
        #pragma unroll
        for (int k = 0; k < 4; k++) {
            int e = lane + 32*k;
            out[rowH + e] = (v[k] - mu)*isd*gs[e] + bts[e];
        }
    }
}

// ---------------- launch ----------------
extern "C" void kernel_launch(void* const* d_in, const int* in_sizes, int n_in,
                              void* d_out, int out_size) {
    const float* H      = (const float*)d_in[0];
    const float* R      = (const float*)d_in[1];
    const float* deltaH = (const float*)d_in[2];
    const float* Wq     = (const float*)d_in[3];
    const float* bq     = (const float*)d_in[4];
    const float* Wk     = (const float*)d_in[5];
    const float* bk     = (const float*)d_in[6];
    const float* Wr     = (const float*)d_in[7];
    const float* br     = (const float*)d_in[8];
    const float* Wf     = (const float*)d_in[9];
    const float* bf     = (const float*)d_in[10];
    const float* gamma  = (const float*)d_in[11];
    const float* beta   = (const float*)d_in[12];
    float* out = (float*)d_out;

    kprep<<<1, 128>>>(Wq, bq, Wr, br);
    kw_build<<<256, 256>>>(Wq, Wk, Wf);
    kw4t<<<64, 256>>>(Wf);
    kconv_H<<<8192, 256>>>(H);
    k0a<<<BB*NN, 256>>>(deltaH);
    k0b<<<64, 256>>>();
    k1m<<<dim3(4, 512), 256>>>(bq, bk);
    kp_P<<<BB*NN, 256>>>(H);
    k2m<<<dim3(2, 2, BB*TT), 256>>>();
    ksoft<<<BB*NN, 256>>>(R);
    kwr<<<BB*NN, 256>>>(R);
    k3m<<<dim3(1, 2, BB*TT), 256>>>();
    kfin<<<BB*NN, 256>>>(H, Wf, bf, gamma, beta, out);
}

// round 10
// speedup vs baseline: 1.0963x; 1.0963x over previous
#include <cuda_runtime.h>
#include <cuda_bf16.h>
#include <math.h>
#include <stdint.h>

#define BB 4
#define NN 256
#define TT 64
#define DD 128
#define DR 32
#define DH 128
#define WF_LD (3*DD+DR)   // 416

// ---------------- device scratch ----------------
__device__ float g_A   [(size_t)BB*NN*TT*DD];   // (b,n,t,e)
__device__ float g_S   [(size_t)BB*TT*NN*NN];   // (b,t,i,j) scores
__device__ float g_Z2  [(size_t)BB*TT*NN*DD];   // (b,t,i,e)
__device__ float g_P   [BB*NN*TT*DR];   // (b,i,t,r)
__device__ float g_qbr [BB*NN*TT];
__device__ float g_wsum[BB*NN*TT];      // (b,i,t)
__device__ float g_WR  [BB*NN*TT*DR];   // (b,i,t,r)
__device__ float g_Ej  [BB*NN*DD];      // (b,j,e)
__device__ float g_dsum[BB*NN*DD];
__device__ float g_W4t [DD*DD];         // [dd][e]
__device__ float g_WQR [DD*DR];
__device__ float g_brq [DR];
__device__ float g_wqbr[DD];
__device__ float g_c0;

// bf16 split operands
__device__ __nv_bfloat16 g_Hh [(size_t)BB*NN*TT*DD];
__device__ __nv_bfloat16 g_Hl [(size_t)BB*NN*TT*DD];
__device__ __nv_bfloat16 g_Wch[4*DH*DD];
__device__ __nv_bfloat16 g_Wcl[4*DH*DD];
__device__ __nv_bfloat16 g_qh [(size_t)BB*TT*NN*DH];
__device__ __nv_bfloat16 g_ql [(size_t)BB*TT*NN*DH];
__device__ __nv_bfloat16 g_kh [(size_t)BB*TT*NN*DH];
__device__ __nv_bfloat16 g_kl [(size_t)BB*TT*NN*DH];
__device__ __nv_bfloat16 g_Bph[(size_t)BB*TT*NN*DD];
__device__ __nv_bfloat16 g_Bpl[(size_t)BB*TT*NN*DD];
__device__ __nv_bfloat16 g_wh [(size_t)BB*TT*NN*NN];
__device__ __nv_bfloat16 g_wl [(size_t)BB*TT*NN*NN];

// ---------------- helpers ----------------
__device__ __forceinline__ void split2(float x, __nv_bfloat16* ph, __nv_bfloat16* pl) {
    __nv_bfloat16 h = __float2bfloat16(x);
    *ph = h;
    *pl = __float2bfloat16(x - __bfloat162float(h));
}
__device__ __forceinline__ uint32_t smem_u32p(const void* p) {
    return (uint32_t)__cvta_generic_to_shared(p);
}
__device__ __forceinline__ void ldsm4(uint32_t& r0, uint32_t& r1, uint32_t& r2, uint32_t& r3, uint32_t a) {
    asm volatile("ldmatrix.sync.aligned.m8n8.x4.shared.b16 {%0,%1,%2,%3}, [%4];"
                 : "=r"(r0), "=r"(r1), "=r"(r2), "=r"(r3) : "r"(a));
}
__device__ __forceinline__ void ldsm4t(uint32_t& r0, uint32_t& r1, uint32_t& r2, uint32_t& r3, uint32_t a) {
    asm volatile("ldmatrix.sync.aligned.m8n8.x4.trans.shared.b16 {%0,%1,%2,%3}, [%4];"
                 : "=r"(r0), "=r"(r1), "=r"(r2), "=r"(r3) : "r"(a));
}
__device__ __forceinline__ void mma16816(float* c, const uint32_t* a, const uint32_t* b) {
    asm volatile("mma.sync.aligned.m16n8k16.row.col.f32.bf16.bf16.f32 "
                 "{%0,%1,%2,%3},{%4,%5,%6,%7},{%8,%9},{%0,%1,%2,%3};"
                 : "+f"(c[0]), "+f"(c[1]), "+f"(c[2]), "+f"(c[3])
                 : "r"(a[0]), "r"(a[1]), "r"(a[2]), "r"(a[3]), "r"(b[0]), "r"(b[1]));
}

// ---------------- kprep: fold Wq into Wr path ----------------
__global__ void kprep(const float* __restrict__ Wq, const float* __restrict__ bq,
                      const float* __restrict__ Wr, const float* __restrict__ br) {
    int d = threadIdx.x; // 128
    float acc[DR];
    #pragma unroll
    for (int r = 0; r < DR; r++) acc[r] = 0.f;
    float wq_br = 0.f;
    for (int h = 0; h < DH; h++) {
        float a = Wq[h*DD + d];
        wq_br += a * br[h];
        #pragma unroll
        for (int r = 0; r < DR; r++) acc[r] += a * Wr[h*DR + r];
    }
    #pragma unroll
    for (int r = 0; r < DR; r++) g_WQR[d*DR + r] = acc[r];
    g_wqbr[d] = wq_br;
    if (d < DR) {
        float s = 0.f;
        for (int h = 0; h < DH; h++) s += bq[h] * Wr[h*DR + d];
        g_brq[d] = s;
    }
    if (d == 0) {
        float s = 0.f;
        for (int h = 0; h < DH; h++) s += bq[h] * br[h];
        g_c0 = s;
    }
}

// ---------------- kw: build concatenated weights + transposed W4 ----------------
__global__ void kw_build(const float* __restrict__ Wq, const float* __restrict__ Wk,
                         const float* __restrict__ Wf) {
    int idx = blockIdx.x*blockDim.x + threadIdx.x;
    if (idx >= 4*DH*DD) return;
    int r = idx / DD, c = idx - r*DD;
    float v;
    if      (r < DH)   v = Wq[r*DD + c];
    else if (r < 2*DH) v = Wk[(r-DH)*DD + c];
    else if (r < 3*DH) v = Wf[(r-2*DH)*WF_LD + c];          // W1
    else               v = Wf[(r-3*DH)*WF_LD + DD + c];     // W2
    split2(v, &g_Wch[idx], &g_Wcl[idx]);
}

__global__ void kw4t(const float* __restrict__ Wf) {
    int f = blockIdx.x*256 + threadIdx.x;   // 16384
    int e = f >> 7, dd = f & 127;
    g_W4t[dd*DD + e] = Wf[e*WF_LD + 2*DD + DR + dd];
}

// ---------------- kconv_H: H fp32 -> bf16 hi/lo (float4) ----------------
__global__ void kconv_H(const float* __restrict__ H) {
    int i = blockIdx.x*blockDim.x + threadIdx.x;   // float4 index
    float4 x = ((const float4*)H)[i];
    __nv_bfloat16 h0,l0,h1,l1,h2,l2,h3,l3;
    split2(x.x,&h0,&l0); split2(x.y,&h1,&l1); split2(x.z,&h2,&l2); split2(x.w,&h3,&l3);
    __nv_bfloat162* ph = (__nv_bfloat162*)g_Hh;
    __nv_bfloat162* pl = (__nv_bfloat162*)g_Hl;
    ph[i*2]   = __nv_bfloat162{h0,h1};
    ph[i*2+1] = __nv_bfloat162{h2,h3};
    pl[i*2]   = __nv_bfloat162{l0,l1};
    pl[i*2+1] = __nv_bfloat162{l2,l3};
}

// ---------------- k0a: dsum[b,j,d] = sum_t dH[b,j,t,d] ----------------
__global__ __launch_bounds__(256) void k0a(const float* __restrict__ dH) {
    int bj = blockIdx.x;
    int tid = threadIdx.x;
    int d4 = tid & 31;
    int ts = tid >> 5;
    const float4* p = (const float4*)(dH + (size_t)bj*TT*DD) + d4;
    float4 s = make_float4(0.f,0.f,0.f,0.f);
    #pragma unroll
    for (int t = ts; t < TT; t += 8) {
        float4 v = p[t*32];
        s.x += v.x; s.y += v.y; s.z += v.z; s.w += v.w;
    }
    __shared__ float4 red[8][32];
    red[ts][d4] = s;
    __syncthreads();
    if (ts == 0) {
        float4 a = red[0][d4];
        #pragma unroll
        for (int k = 1; k < 8; k++) {
            float4 b = red[k][d4];
            a.x += b.x; a.y += b.y; a.z += b.z; a.w += b.w;
        }
        ((float4*)(g_dsum + (size_t)bj*DD))[d4] = a;
    }
}

// ---------------- k0b: Ej = dsum @ W4^T (via W4t) ----------------
__global__ __launch_bounds__(256) void k0b() {
    int r0 = blockIdx.x * 16;
    __shared__ float ds[16][DD];
    int tid = threadIdx.x;
    #pragma unroll
    for (int l = 0; l < 8; l++) {
        int f = l*256 + tid;
        ds[f >> 7][f & 127] = g_dsum[(size_t)(r0 + (f >> 7))*DD + (f & 127)];
    }
    __syncthreads();
    int e = tid & 127, rh = tid >> 7;
    float acc[8];
    #pragma unroll
    for (int rr = 0; rr < 8; rr++) acc[rr] = 0.f;
    for (int dd = 0; dd < DD; dd++) {
        float wv = g_W4t[dd*DD + e];
        #pragma unroll
        for (int rr = 0; rr < 8; rr++) acc[rr] += ds[rh*8 + rr][dd]*wv;
    }
    #pragma unroll
    for (int rr = 0; rr < 8; rr++)
        g_Ej[(size_t)(r0 + rh*8 + rr)*DD + e] = acc[rr];
}

// ================= split-GEMM core (resident hi/lo tiles, k-chunk 32) =================

// ---------------- k1m: fused projection GEMM ----------------
__global__ __launch_bounds__(256) void k1m(const float* __restrict__ bq,
                                           const float* __restrict__ bk) {
    __shared__ __align__(16) __nv_bfloat16 Ahs[128][40];
    __shared__ __align__(16) __nv_bfloat16 Als[128][40];
    __shared__ __align__(16) __nv_bfloat16 Bhs[128][40];
    __shared__ __align__(16) __nv_bfloat16 Bls[128][40];
    __shared__ float biasq[DH], biask[DH];
    int tid = threadIdx.x, lane = tid & 31, w = tid >> 5;
    int wm = w & 1, wn = w >> 1;
    if (tid < DH) { biasq[tid] = bq[tid]; biask[tid] = bk[tid]; }
    const int n0 = blockIdx.x * 128;
    const int m0 = blockIdx.y * 128;
    float acc[4][4][4];
    #pragma unroll
    for (int i = 0; i < 4; i++)
        #pragma unroll
        for (int j = 0; j < 4; j++)
            #pragma unroll
            for (int r = 0; r < 4; r++) acc[i][j][r] = 0.f;
    uint32_t ahb = smem_u32p(&Ahs[0][0]);
    uint32_t alb = smem_u32p(&Als[0][0]);
    uint32_t bhb = smem_u32p(&Bhs[0][0]);
    uint32_t blb = smem_u32p(&Bls[0][0]);
    const uint32_t* Ah32 = (const uint32_t*)g_Hh;
    const uint32_t* Al32 = (const uint32_t*)g_Hl;
    const uint32_t* Bh32 = (const uint32_t*)g_Wch;
    const uint32_t* Bl32 = (const uint32_t*)g_Wcl;

    auto loadT = [&](uint32_t* dst, const uint32_t* src, int row0, int c) {
        #pragma unroll
        for (int l = 0; l < 8; l++) {
            int f = l*256 + tid; int r = f >> 4, cu = f & 15;
            dst[r*20 + cu] = src[(size_t)(row0 + r)*64 + c*16 + cu];
        }
    };

    #pragma unroll 1
    for (int c = 0; c < 4; c++) {   // 4 chunks of 32 k
        loadT((uint32_t*)Ahs, Ah32, m0, c);
        loadT((uint32_t*)Als, Al32, m0, c);
        loadT((uint32_t*)Bhs, Bh32, n0, c);
        loadT((uint32_t*)Bls, Bl32, n0, c);
        __syncthreads();
        #pragma unroll
        for (int ki = 0; ki < 2; ki++) {
            uint32_t ah[4][4], al[4][4], bh[4][2], bl[4][2];
            #pragma unroll
            for (int mf = 0; mf < 4; mf++) {
                uint32_t off = ((wm*64 + mf*16 + (lane & 15))*40 + ki*16 + (lane >> 4)*8)*2;
                ldsm4(ah[mf][0], ah[mf][1], ah[mf][2], ah[mf][3], ahb + off);
                ldsm4(al[mf][0], al[mf][1], al[mf][2], al[mf][3], alb + off);
            }
            #pragma unroll
            for (int g = 0; g < 2; g++) {
                uint32_t off = ((wn*32 + g*16 + (lane & 15))*40 + ki*16 + (lane >> 4)*8)*2;
                uint32_t r0, r1, r2, r3;
                ldsm4(r0, r1, r2, r3, bhb + off);
                bh[g*2][0] = r0; bh[g*2][1] = r2; bh[g*2+1][0] = r1; bh[g*2+1][1] = r3;
                ldsm4(r0, r1, r2, r3, blb + off);
                bl[g*2][0] = r0; bl[g*2][1] = r2; bl[g*2+1][0] = r1; bl[g*2+1][1] = r3;
            }
            #pragma unroll
            for (int mf = 0; mf < 4; mf++)
                #pragma unroll
                for (int nf = 0; nf < 4; nf++) {
                    mma16816(acc[mf][nf], ah[mf], bh[nf]);
                    mma16816(acc[mf][nf], al[mf], bh[nf]);
                    mma16816(acc[mf][nf], ah[mf], bl[nf]);
                }
        }
        __syncthreads();
    }
    // epilogue
    int seg = blockIdx.x;  // 0:q 1:k 2:A 3:Bp
    #pragma unroll
    for (int mf = 0; mf < 4; mf++)
        #pragma unroll
        for (int nf = 0; nf < 4; nf++)
            #pragma unroll
            for (int r = 0; r < 4; r++) {
                int m = m0 + wm*64 + mf*16 + (lane >> 2) + ((r >> 1) << 3);
                int nl = wn*32 + nf*8 + ((lane & 3) << 1) + (r & 1);
                float v = acc[mf][nf][r];
                int b_ = m >> 14, nn = (m >> 6) & 255, t = m & 63;
                size_t base = (size_t)((b_*TT + t)*NN + nn);
                if (seg == 0) {
                    size_t d = base*DH + nl;
                    split2(v + biasq[nl], g_qh + d, g_ql + d);
                } else if (seg == 1) {
                    size_t d = base*DH + nl;
                    split2(v + biask[nl], g_kh + d, g_kl + d);
                } else if (seg == 2) {
                    g_A[(size_t)m*DD + nl] = v;
                } else {
                    float bpv = v + g_Ej[(size_t)(b_*NN + nn)*DD + nl];
                    size_t d = base*DD + nl;
                    split2(bpv, g_Bph + d, g_Bpl + d);
                }
            }
}

// ---------------- k2m: scores per (b,t): Q @ K^T ----------------
__global__ __launch_bounds__(256) void k2m() {
    __shared__ __align__(16) __nv_bfloat16 Ahs[128][40];
    __shared__ __align__(16) __nv_bfloat16 Als[128][40];
    __shared__ __align__(16) __nv_bfloat16 Bhs[128][40];
    __shared__ __align__(16) __nv_bfloat16 Bls[128][40];
    int tid = threadIdx.x, lane = tid & 31, w = tid >> 5;
    int wm = w & 1, wn = w >> 1;
    int bt = blockIdx.z;
    const int n0 = blockIdx.x * 128;
    const int m0 = blockIdx.y * 128;
    float acc[4][4][4];
    #pragma unroll
    for (int i = 0; i < 4; i++)
        #pragma unroll
        for (int j = 0; j < 4; j++)
            #pragma unroll
            for (int r = 0; r < 4; r++) acc[i][j][r] = 0.f;
    uint32_t ahb = smem_u32p(&Ahs[0][0]);
    uint32_t alb = smem_u32p(&Als[0][0]);
    uint32_t bhb = smem_u32p(&Bhs[0][0]);
    uint32_t blb = smem_u32p(&Bls[0][0]);
    const uint32_t* qh32 = (const uint32_t*)g_qh + (size_t)bt*NN*64;
    const uint32_t* ql32 = (const uint32_t*)g_ql + (size_t)bt*NN*64;
    const uint32_t* kh32 = (const uint32_t*)g_kh + (size_t)bt*NN*64;
    const uint32_t* kl32 = (const uint32_t*)g_kl + (size_t)bt*NN*64;

    auto loadT = [&](uint32_t* dst, const uint32_t* src, int row0, int c) {
        #pragma unroll
        for (int l = 0; l < 8; l++) {
            int f = l*256 + tid; int r = f >> 4, cu = f & 15;
            dst[r*20 + cu] = src[(size_t)(row0 + r)*64 + c*16 + cu];
        }
    };

    #pragma unroll 1
    for (int c = 0; c < 4; c++) {
        loadT((uint32_t*)Ahs, qh32, m0, c);
        loadT((uint32_t*)Als, ql32, m0, c);
        loadT((uint32_t*)Bhs, kh32, n0, c);
        loadT((uint32_t*)Bls, kl32, n0, c);
        __syncthreads();
        #pragma unroll
        for (int ki = 0; ki < 2; ki++) {
            uint32_t ah[4][4], al[4][4], bh[4][2], bl[4][2];
            #pragma unroll
            for (int mf = 0; mf < 4; mf++) {
                uint32_t off = ((wm*64 + mf*16 + (lane & 15))*40 + ki*16 + (lane >> 4)*8)*2;
                ldsm4(ah[mf][0], ah[mf][1], ah[mf][2], ah[mf][3], ahb + off);
                ldsm4(al[mf][0], al[mf][1], al[mf][2], al[mf][3], alb + off);
            }
            #pragma unroll
            for (int g = 0; g < 2; g++) {
                uint32_t off = ((wn*32 + g*16 + (lane & 15))*40 + ki*16 + (lane >> 4)*8)*2;
                uint32_t r0, r1, r2, r3;
                ldsm4(r0, r1, r2, r3, bhb + off);
                bh[g*2][0] = r0; bh[g*2][1] = r2; bh[g*2+1][0] = r1; bh[g*2+1][1] = r3;
                ldsm4(r0, r1, r2, r3, blb + off);
                bl[g*2][0] = r0; bl[g*2][1] = r2; bl[g*2+1][0] = r1; bl[g*2+1][1] = r3;
            }
            #pragma unroll
            for (int mf = 0; mf < 4; mf++)
                #pragma unroll
                for (int nf = 0; nf < 4; nf++) {
                    mma16816(acc[mf][nf], ah[mf], bh[nf]);
                    mma16816(acc[mf][nf], al[mf], bh[nf]);
                    mma16816(acc[mf][nf], ah[mf], bl[nf]);
                }
        }
        __syncthreads();
    }
    float* C = g_S + (size_t)bt*NN*NN;
    #pragma unroll
    for (int mf = 0; mf < 4; mf++)
        #pragma unroll
        for (int nf = 0; nf < 4; nf++) {
            int m = m0 + wm*64 + mf*16 + (lane >> 2);
            int n = n0 + wn*32 + nf*8 + ((lane & 3) << 1);
            float2 v0 = make_float2(acc[mf][nf][0], acc[mf][nf][1]);
            float2 v1 = make_float2(acc[mf][nf][2], acc[mf][nf][3]);
            *(float2*)&C[(size_t)m*NN + n] = v0;
            *(float2*)&C[(size_t)(m + 8)*NN + n] = v1;
        }
}

// ---------------- ksoft ----------------
__global__ __launch_bounds__(256) void ksoft(const float* __restrict__ R) {
    int bi = blockIdx.x; int b = bi >> 8, i = bi & 255;
    int j = threadIdx.x;
    __shared__ float Ps[TT][DR];
    __shared__ float qbrs[TT];
    __shared__ float ws[TT];
    #pragma unroll
    for (int l = 0; l < 8; l++) {
        int f = l*256 + j; int t = f >> 5, r = f & 31;
        Ps[t][r] = g_P[((size_t)bi*TT + t)*DR + r];
    }
    if (j < TT) { qbrs[j] = g_qbr[(size_t)bi*TT + j]; ws[j] = 0.f; }
    __syncthreads();
    float Rr[DR];
    const float* Rp = R + ((size_t)bi*NN + j)*DR;
    #pragma unroll
    for (int r4 = 0; r4 < 8; r4++) {
        float4 v = *(const float4*)(Rp + r4*4);
        Rr[r4*4+0] = v.x; Rr[r4*4+1] = v.y; Rr[r4*4+2] = v.z; Rr[r4*4+3] = v.w;
    }
    float sv[TT];
    const float rs = 0.08838834764831845f;  // 1/sqrt(128)
    size_t sbase = ((size_t)b*TT*NN + i)*NN + j;
    #pragma unroll
    for (int t = 0; t < TT; t++) {
        float qk = g_S[sbase + (size_t)t*NN*NN];
        float rt = 0.f;
        #pragma unroll
        for (int r = 0; r < DR; r++) rt += Ps[t][r]*Rr[r];
        sv[t] = (qk + rt + qbrs[t])*rs;
    }
    float mx = sv[0];
    #pragma unroll
    for (int t = 1; t < TT; t++) mx = fmaxf(mx, sv[t]);
    float sum = 0.f;
    #pragma unroll
    for (int t = 0; t < TT; t++) { sv[t] = __expf(sv[t]-mx); sum += sv[t]; }
    float inv = (j == i) ? 0.f : (1.f/sum);
    int lane = j & 31;
    #pragma unroll
    for (int t = 0; t < TT; t++) {
        float wv = sv[t]*inv;
        size_t idx = sbase + (size_t)t*NN*NN;
        split2(wv, g_wh + idx, g_wl + idx);
        float red = wv;
        #pragma unroll
        for (int o = 16; o; o >>= 1) red += __shfl_xor_sync(0xffffffffu, red, o);
        if (lane == 0) atomicAdd(&ws[t], red);
    }
    __syncthreads();
    if (j < TT) g_wsum[(size_t)bi*TT + j] = ws[j];
}

// ---------------- kp: P = H @ WQR + brq ; qbr = H @ wqbr + c0 ----------------
__global__ __launch_bounds__(256) void kp_P(const float* __restrict__ H) {
    int bi = blockIdx.x;
    __shared__ float Hs[TT][33];
    __shared__ float Ws[32][DR];
    __shared__ float wqbrs[32];
    int tid = threadIdx.x;
    int t = tid >> 2, rg = (tid & 3)*8;
    float acc[8];
    #pragma unroll
    for (int r = 0; r < 8; r++) acc[r] = 0.f;
    float qacc = 0.f;
    const float* Hbase = H + (size_t)bi*TT*DD;
    for (int d0 = 0; d0 < DD; d0 += 32) {
        #pragma unroll
        for (int l = 0; l < 8; l++) {
            int f = l*256 + tid; int t2 = f >> 5, dd = f & 31;
            Hs[t2][dd] = Hbase[t2*DD + d0 + dd];
        }
        #pragma unroll
        for (int l = 0; l < 4; l++) {
            int f = l*256 + tid; int dd = f >> 5, r = f & 31;
            Ws[dd][r] = g_WQR[(d0 + dd)*DR + r];
        }
        if (tid < 32) wqbrs[tid] = g_wqbr[d0 + tid];
        __syncthreads();
        #pragma unroll
        for (int dd = 0; dd < 32; dd++) {
            float a = Hs[t][dd];
            #pragma unroll
            for (int rr = 0; rr < 8; rr++) acc[rr] += a * Ws[dd][rg + rr];
            qacc += a * wqbrs[dd];
        }
        __syncthreads();
    }
    size_t pb = ((size_t)bi*TT + t)*DR + rg;
    #pragma unroll
    for (int rr = 0; rr < 8; rr++) g_P[pb + rr] = acc[rr] + g_brq[rg + rr];
    if (rg == 0) g_qbr[(size_t)bi*TT + t] = qacc + g_c0;
}

// ---------------- kwr: WR[b,i,t,r] = sum_j w * R (w = wh+wl) ----------------
__global__ __launch_bounds__(256) void kwr(const float* __restrict__ R) {
    int bi = blockIdx.x; int b = bi >> 8, i = bi & 255;
    __shared__ float Rs[32][33];
    __shared__ float wsm[TT][33];
    int tid = threadIdx.x;
    int t = tid >> 2, rg = (tid & 3)*8;
    float acc[8];
    #pragma unroll
    for (int r = 0; r < 8; r++) acc[r] = 0.f;
    for (int j0 = 0; j0 < NN; j0 += 32) {
        #pragma unroll
        for (int l = 0; l < 4; l++) {
            int f = l*256 + tid; int jj = f >> 5, r = f & 31;
            Rs[jj][r] = R[((size_t)bi*NN + j0 + jj)*DR + r];
        }
        #pragma unroll
        for (int l = 0; l < 8; l++) {
            int f = l*256 + tid; int t2 = f >> 5, jj = f & 31;
            size_t idx = ((size_t)(b*TT + t2)*NN + i)*NN + j0 + jj;
            wsm[t2][jj] = __bfloat162float(g_wh[idx]) + __bfloat162float(g_wl[idx]);
        }
        __syncthreads();
        #pragma unroll
        for (int jj = 0; jj < 32; jj++) {
            float wv = wsm[t][jj];
            #pragma unroll
            for (int rr = 0; rr < 8; rr++) acc[rr] += wv * Rs[jj][rg + rr];
        }
        __syncthreads();
    }
    size_t ob = ((size_t)bi*TT + t)*DR + rg;
    #pragma unroll
    for (int rr = 0; rr < 8; rr++) g_WR[ob + rr] = acc[rr];
}

// ---------------- k3m: z2 per (b,t): w @ Bp ----------------
__global__ __launch_bounds__(256) void k3m() {
    __shared__ __align__(16) __nv_bfloat16 Ahs[128][40];  // w hi: 128 i x 32 j
    __shared__ __align__(16) __nv_bfloat16 Als[128][40];  // w lo
    __shared__ __align__(16) __nv_bfloat16 Bhs[32][136];  // Bp hi: 32 j x 128 e
    __shared__ __align__(16) __nv_bfloat16 Bls[32][136];  // Bp lo
    int tid = threadIdx.x, lane = tid & 31, w = tid >> 5;
    int wm = w & 1, wn = w >> 1;
    int bt = blockIdx.z;
    const int m0 = blockIdx.y * 128;
    float acc[4][4][4];
    #pragma unroll
    for (int i = 0; i < 4; i++)
        #pragma unroll
        for (int j = 0; j < 4; j++)
            #pragma unroll
            for (int r = 0; r < 4; r++) acc[i][j][r] = 0.f;
    uint32_t ahb = smem_u32p(&Ahs[0][0]);
    uint32_t alb = smem_u32p(&Als[0][0]);
    uint32_t bhb = smem_u32p(&Bhs[0][0]);
    uint32_t blb = smem_u32p(&Bls[0][0]);
    const uint32_t* wh32  = (const uint32_t*)g_wh  + (size_t)bt*NN*(NN/2);
    const uint32_t* wl32  = (const uint32_t*)g_wl  + (size_t)bt*NN*(NN/2);
    const uint32_t* bph32 = (const uint32_t*)g_Bph + (size_t)bt*NN*(DD/2);
    const uint32_t* bpl32 = (const uint32_t*)g_Bpl + (size_t)bt*NN*(DD/2);

    auto loadA = [&](uint32_t* dst, const uint32_t* src, int c) {
        #pragma unroll
        for (int l = 0; l < 8; l++) {
            int f = l*256 + tid; int r = f >> 4, cu = f & 15;
            dst[r*20 + cu] = src[(size_t)(m0 + r)*128 + c*16 + cu];
        }
    };
    auto loadB = [&](uint32_t* dst, const uint32_t* src, int c) {
        #pragma unroll
        for (int l = 0; l < 8; l++) {
            int f = l*256 + tid; int r = f >> 6, cu = f & 63;
            dst[r*68 + cu] = src[(size_t)(c*32 + r)*64 + cu];
        }
    };

    #pragma unroll 1
    for (int c = 0; c < 8; c++) {   // K=256 in chunks of 32
        loadA((uint32_t*)Ahs, wh32, c);
        loadA((uint32_t*)Als, wl32, c);
        loadB((uint32_t*)Bhs, bph32, c);
        loadB((uint32_t*)Bls, bpl32, c);
        __syncthreads();
        #pragma unroll
        for (int ki = 0; ki < 2; ki++) {
            uint32_t ah[4][4], al[4][4], bh[4][2], bl[4][2];
            #pragma unroll
            for (int mf = 0; mf < 4; mf++) {
                uint32_t off = ((wm*64 + mf*16 + (lane & 15))*40 + ki*16 + (lane >> 4)*8)*2;
                ldsm4(ah[mf][0], ah[mf][1], ah[mf][2], ah[mf][3], ahb + off);
                ldsm4(al[mf][0], al[mf][1], al[mf][2], al[mf][3], alb + off);
            }
            #pragma unroll
            for (int g = 0; g < 2; g++) {
                uint32_t off = ((ki*16 + (lane & 15))*136 + wn*32 + g*16 + (lane >> 4)*8)*2;
                uint32_t r0, r1, r2, r3;
                ldsm4t(r0, r1, r2, r3, bhb + off);
                bh[g*2][0] = r0; bh[g*2][1] = r1; bh[g*2+1][0] = r2; bh[g*2+1][1] = r3;
                ldsm4t(r0, r1, r2, r3, blb + off);
                bl[g*2][0] = r0; bl[g*2][1] = r1; bl[g*2+1][0] = r2; bl[g*2+1][1] = r3;
            }
            #pragma unroll
            for (int mf = 0; mf < 4; mf++)
                #pragma unroll
                for (int nf = 0; nf < 4; nf++) {
                    mma16816(acc[mf][nf], ah[mf], bh[nf]);
                    mma16816(acc[mf][nf], al[mf], bh[nf]);
                    mma16816(acc[mf][nf], ah[mf], bl[nf]);
                }
        }
        __syncthreads();
    }
    float* C = g_Z2 + (size_t)bt*NN*DD;
    #pragma unroll
    for (int mf = 0; mf < 4; mf++)
        #pragma unroll
        for (int nf = 0; nf < 4; nf++) {
            int m = m0 + wm*64 + mf*16 + (lane >> 2);
            int n = wn*32 + nf*8 + ((lane & 3) << 1);
            float2 v0 = make_float2(acc[mf][nf][0], acc[mf][nf][1]);
            float2 v1 = make_float2(acc[mf][nf][2], acc[mf][nf][3]);
            *(float2*)&C[(size_t)m*DD + n] = v0;
            *(float2*)&C[(size_t)(m + 8)*DD + n] = v1;
        }
}

// ---------------- kfin: warp-per-row z assembly + residual + LayerNorm ----------------
__global__ __launch_bounds__(256) void kfin(const float* __restrict__ H,
                                            const float* __restrict__ Wf,
                                            const float* __restrict__ bf,
                                            const float* __restrict__ gamma,
                                            const float* __restrict__ beta,
                                            float* __restrict__ out) {
    int bi = blockIdx.x; int b = bi >> 8, i = bi & 255;
    __shared__ float W3s[DD][33];
    __shared__ float WRs[TT][DR];
    __shared__ float wsums[TT];
    __shared__ float bfs[DD], gs[DD], bts[DD];
    int tid = threadIdx.x;
    #pragma unroll
    for (int l = 0; l < 16; l++) {
        int f = l*256 + tid; int e = f >> 5, r = f & 31;
        W3s[e][r] = Wf[e*WF_LD + 2*DD + r];
    }
    #pragma unroll
    for (int l = 0; l < 8; l++) {
        int f = l*256 + tid; int t = f >> 5, r = f & 31;
        WRs[t][r] = g_WR[((size_t)bi*TT + t)*DR + r];
    }
    if (tid < TT) wsums[tid] = g_wsum[(size_t)bi*TT + tid];
    if (tid < DD) { bfs[tid] = bf[tid]; gs[tid] = gamma[tid]; bts[tid] = beta[tid]; }
    __syncthreads();
    int lane = tid & 31, w = tid >> 5;
    #pragma unroll 1
    for (int pass = 0; pass < 8; pass++) {
        int t = pass*8 + w;
        size_t rowH = ((size_t)bi*TT + t)*DD;
        size_t rowZ = ((size_t)(b*TT + t)*NN + i)*DD;
        float wst = wsums[t];
        float z3[4];
        #pragma unroll
        for (int k = 0; k < 4; k++) z3[k] = 0.f;
        #pragma unroll
        for (int r = 0; r < DR; r++) {
            float wr = WRs[t][r];
            #pragma unroll
            for (int k = 0; k < 4; k++) z3[k] += wr * W3s[lane + 32*k][r];
        }
        float v[4], s1 = 0.f, s2 = 0.f;
        #pragma unroll
        for (int k = 0; k < 4; k++) {
            int e = lane + 32*k;
            float x = H[rowH + e] + (g_A[rowH + e] + bfs[e])*wst + g_Z2[rowZ + e] + z3[k];
            v[k] = x; s1 += x; s2 += x*x;
        }
        #pragma unroll
        for (int o = 16; o; o >>= 1) {
            s1 += __shfl_xor_sync(0xffffffffu, s1, o);
            s2 += __shfl_xor_sync(0xffffffffu, s2, o);
        }
        float mu = s1*(1.f/128.f);
        float var = s2*(1.f/128.f) - mu*mu;
        float isd = rsqrtf(var + 1e-5f);
        #pragma unroll
        for (int k = 0; k < 4; k++) {
            int e = lane + 32*k;
            out[rowH + e] = (v[k] - mu)*isd*gs[e] + bts[e];
        }
    }
}

// ---------------- launch ----------------
extern "C" void kernel_launch(void* const* d_in, const int* in_sizes, int n_in,
                              void* d_out, int out_size) {
    const float* H      = (const float*)d_in[0];
    const float* R      = (const float*)d_in[1];
    const float* deltaH = (const float*)d_in[2];
    const float* Wq     = (const float*)d_in[3];
    const float* bq     = (const float*)d_in[4];
    const float* Wk     = (const float*)d_in[5];
    const float* bk     = (const float*)d_in[6];
    const float* Wr     = (const float*)d_in[7];
    const float* br     = (const float*)d_in[8];
    const float* Wf     = (const float*)d_in[9];
    const float* bf     = (const float*)d_in[10];
    const float* gamma  = (const float*)d_in[11];
    const float* beta   = (const float*)d_in[12];
    float* out = (float*)d_out;

    kprep<<<1, 128>>>(Wq, bq, Wr, br);
    kw_build<<<256, 256>>>(Wq, Wk, Wf);
    kw4t<<<64, 256>>>(Wf);
    kconv_H<<<8192, 256>>>(H);
    k0a<<<BB*NN, 256>>>(deltaH);
    k0b<<<64, 256>>>();
    k1m<<<dim3(4, 512), 256>>>(bq, bk);
    kp_P<<<BB*NN, 256>>>(H);
    k2m<<<dim3(2, 2, BB*TT), 256>>>();
    ksoft<<<BB*NN, 256>>>(R);
    kwr<<<BB*NN, 256>>>(R);
    k3m<<<dim3(1, 2, BB*TT), 256>>>();
    kfin<<<BB*NN, 256>>>(H, Wf, bf, gamma, beta, out);
}

// round 11
// speedup vs baseline: 1.2410x; 1.1320x over previous
#include <cuda_runtime.h>
#include <cuda_bf16.h>
#include <math.h>
#include <stdint.h>

#define BB 4
#define NN 256
#define TT 64
#define DD 128
#define DR 32
#define DH 128
#define WF_LD (3*DD+DR)   // 416

// ---------------- device scratch ----------------
__device__ float g_A   [(size_t)BB*NN*TT*DD];   // (b,n,t,e)
__device__ float g_S   [(size_t)BB*TT*NN*NN];   // (b,t,i,j) scores
__device__ float g_Z2  [(size_t)BB*TT*NN*DD];   // (b,t,i,e)
__device__ float g_P   [BB*NN*TT*DR];   // (b,i,t,r)
__device__ float g_qbr [BB*NN*TT];
__device__ float g_wsum[BB*NN*TT];      // (b,i,t)
__device__ float g_WR  [BB*NN*TT*DR];   // (b,i,t,r)
__device__ float g_Ej  [BB*NN*DD];      // (b,j,e)
__device__ float g_dsum[BB*NN*DD];
__device__ float g_W4t [DD*DD];         // [dd][e]
__device__ float g_WQR [DD*DR];
__device__ float g_brq [DR];
__device__ float g_wqbr[DD];
__device__ float g_c0;

// bf16 split operands (128B aligned for uint4 access)
__device__ __align__(128) __nv_bfloat16 g_Hh [(size_t)BB*NN*TT*DD];
__device__ __align__(128) __nv_bfloat16 g_Hl [(size_t)BB*NN*TT*DD];
__device__ __align__(128) __nv_bfloat16 g_Wch[4*DH*DD];
__device__ __align__(128) __nv_bfloat16 g_Wcl[4*DH*DD];
__device__ __align__(128) __nv_bfloat16 g_qh [(size_t)BB*TT*NN*DH];
__device__ __align__(128) __nv_bfloat16 g_ql [(size_t)BB*TT*NN*DH];
__device__ __align__(128) __nv_bfloat16 g_kh [(size_t)BB*TT*NN*DH];
__device__ __align__(128) __nv_bfloat16 g_kl [(size_t)BB*TT*NN*DH];
__device__ __align__(128) __nv_bfloat16 g_Bph[(size_t)BB*TT*NN*DD];
__device__ __align__(128) __nv_bfloat16 g_Bpl[(size_t)BB*TT*NN*DD];
__device__ __align__(128) __nv_bfloat16 g_wh [(size_t)BB*TT*NN*NN];
__device__ __align__(128) __nv_bfloat16 g_wl [(size_t)BB*TT*NN*NN];

// ---------------- helpers ----------------
__device__ __forceinline__ void split2(float x, __nv_bfloat16* ph, __nv_bfloat16* pl) {
    __nv_bfloat16 h = __float2bfloat16(x);
    *ph = h;
    *pl = __float2bfloat16(x - __bfloat162float(h));
}
__device__ __forceinline__ uint32_t smem_u32p(const void* p) {
    return (uint32_t)__cvta_generic_to_shared(p);
}
__device__ __forceinline__ void ldsm4(uint32_t& r0, uint32_t& r1, uint32_t& r2, uint32_t& r3, uint32_t a) {
    asm volatile("ldmatrix.sync.aligned.m8n8.x4.shared.b16 {%0,%1,%2,%3}, [%4];"
                 : "=r"(r0), "=r"(r1), "=r"(r2), "=r"(r3) : "r"(a));
}
__device__ __forceinline__ void ldsm4t(uint32_t& r0, uint32_t& r1, uint32_t& r2, uint32_t& r3, uint32_t a) {
    asm volatile("ldmatrix.sync.aligned.m8n8.x4.trans.shared.b16 {%0,%1,%2,%3}, [%4];"
                 : "=r"(r0), "=r"(r1), "=r"(r2), "=r"(r3) : "r"(a));
}
__device__ __forceinline__ void mma16816(float* c, const uint32_t* a, const uint32_t* b) {
    asm volatile("mma.sync.aligned.m16n8k16.row.col.f32.bf16.bf16.f32 "
                 "{%0,%1,%2,%3},{%4,%5,%6,%7},{%8,%9},{%0,%1,%2,%3};"
                 : "+f"(c[0]), "+f"(c[1]), "+f"(c[2]), "+f"(c[3])
                 : "r"(a[0]), "r"(a[1]), "r"(a[2]), "r"(a[3]), "r"(b[0]), "r"(b[1]));
}

// ---------------- kprep: fold Wq into Wr path ----------------
__global__ void kprep(const float* __restrict__ Wq, const float* __restrict__ bq,
                      const float* __restrict__ Wr, const float* __restrict__ br) {
    int d = threadIdx.x; // 128
    float acc[DR];
    #pragma unroll
    for (int r = 0; r < DR; r++) acc[r] = 0.f;
    float wq_br = 0.f;
    for (int h = 0; h < DH; h++) {
        float a = Wq[h*DD + d];
        wq_br += a * br[h];
        #pragma unroll
        for (int r = 0; r < DR; r++) acc[r] += a * Wr[h*DR + r];
    }
    #pragma unroll
    for (int r = 0; r < DR; r++) g_WQR[d*DR + r] = acc[r];
    g_wqbr[d] = wq_br;
    if (d < DR) {
        float s = 0.f;
        for (int h = 0; h < DH; h++) s += bq[h] * Wr[h*DR + d];
        g_brq[d] = s;
    }
    if (d == 0) {
        float s = 0.f;
        for (int h = 0; h < DH; h++) s += bq[h] * br[h];
        g_c0 = s;
    }
}

// ---------------- kw: build concatenated weights + transposed W4 ----------------
__global__ void kw_build(const float* __restrict__ Wq, const float* __restrict__ Wk,
                         const float* __restrict__ Wf) {
    int idx = blockIdx.x*blockDim.x + threadIdx.x;
    if (idx >= 4*DH*DD) return;
    int r = idx / DD, c = idx - r*DD;
    float v;
    if      (r < DH)   v = Wq[r*DD + c];
    else if (r < 2*DH) v = Wk[(r-DH)*DD + c];
    else if (r < 3*DH) v = Wf[(r-2*DH)*WF_LD + c];          // W1
    else               v = Wf[(r-3*DH)*WF_LD + DD + c];     // W2
    split2(v, &g_Wch[idx], &g_Wcl[idx]);
}

__global__ void kw4t(const float* __restrict__ Wf) {
    int f = blockIdx.x*256 + threadIdx.x;   // 16384
    int e = f >> 7, dd = f & 127;
    g_W4t[dd*DD + e] = Wf[e*WF_LD + 2*DD + DR + dd];
}

// ---------------- kconv_H: H fp32 -> bf16 hi/lo (float4) ----------------
__global__ void kconv_H(const float* __restrict__ H) {
    int i = blockIdx.x*blockDim.x + threadIdx.x;   // float4 index
    float4 x = ((const float4*)H)[i];
    __nv_bfloat16 h0,l0,h1,l1,h2,l2,h3,l3;
    split2(x.x,&h0,&l0); split2(x.y,&h1,&l1); split2(x.z,&h2,&l2); split2(x.w,&h3,&l3);
    __nv_bfloat162* ph = (__nv_bfloat162*)g_Hh;
    __nv_bfloat162* pl = (__nv_bfloat162*)g_Hl;
    ph[i*2]   = __nv_bfloat162{h0,h1};
    ph[i*2+1] = __nv_bfloat162{h2,h3};
    pl[i*2]   = __nv_bfloat162{l0,l1};
    pl[i*2+1] = __nv_bfloat162{l2,l3};
}

// ---------------- k0a: dsum[b,j,d] = sum_t dH[b,j,t,d] ----------------
__global__ __launch_bounds__(256) void k0a(const float* __restrict__ dH) {
    int bj = blockIdx.x;
    int tid = threadIdx.x;
    int d4 = tid & 31;
    int ts = tid >> 5;
    const float4* p = (const float4*)(dH + (size_t)bj*TT*DD) + d4;
    float4 s = make_float4(0.f,0.f,0.f,0.f);
    #pragma unroll
    for (int t = ts; t < TT; t += 8) {
        float4 v = p[t*32];
        s.x += v.x; s.y += v.y; s.z += v.z; s.w += v.w;
    }
    __shared__ float4 red[8][32];
    red[ts][d4] = s;
    __syncthreads();
    if (ts == 0) {
        float4 a = red[0][d4];
        #pragma unroll
        for (int k = 1; k < 8; k++) {
            float4 b = red[k][d4];
            a.x += b.x; a.y += b.y; a.z += b.z; a.w += b.w;
        }
        ((float4*)(g_dsum + (size_t)bj*DD))[d4] = a;
    }
}

// ---------------- k0b: Ej = dsum @ W4^T (via W4t) ----------------
__global__ __launch_bounds__(256) void k0b() {
    int r0 = blockIdx.x * 16;
    __shared__ float ds[16][DD];
    int tid = threadIdx.x;
    #pragma unroll
    for (int l = 0; l < 8; l++) {
        int f = l*256 + tid;
        ds[f >> 7][f & 127] = g_dsum[(size_t)(r0 + (f >> 7))*DD + (f & 127)];
    }
    __syncthreads();
    int e = tid & 127, rh = tid >> 7;
    float acc[8];
    #pragma unroll
    for (int rr = 0; rr < 8; rr++) acc[rr] = 0.f;
    for (int dd = 0; dd < DD; dd++) {
        float wv = g_W4t[dd*DD + e];
        #pragma unroll
        for (int rr = 0; rr < 8; rr++) acc[rr] += ds[rh*8 + rr][dd]*wv;
    }
    #pragma unroll
    for (int rr = 0; rr < 8; rr++)
        g_Ej[(size_t)(r0 + rh*8 + rr)*DD + e] = acc[rr];
}

// ================= split-GEMM core (resident hi/lo tiles, k-chunk 32, uint4 loads) ==========

// ---------------- k1m: fused projection GEMM ----------------
__global__ __launch_bounds__(256) void k1m(const float* __restrict__ bq,
                                           const float* __restrict__ bk) {
    __shared__ __align__(16) __nv_bfloat16 Ahs[128][40];
    __shared__ __align__(16) __nv_bfloat16 Als[128][40];
    __shared__ __align__(16) __nv_bfloat16 Bhs[128][40];
    __shared__ __align__(16) __nv_bfloat16 Bls[128][40];
    __shared__ float biasq[DH], biask[DH];
    int tid = threadIdx.x, lane = tid & 31, w = tid >> 5;
    int wm = w & 1, wn = w >> 1;
    if (tid < DH) { biasq[tid] = bq[tid]; biask[tid] = bk[tid]; }
    const int n0 = blockIdx.x * 128;
    const int m0 = blockIdx.y * 128;
    float acc[4][4][4];
    #pragma unroll
    for (int i = 0; i < 4; i++)
        #pragma unroll
        for (int j = 0; j < 4; j++)
            #pragma unroll
            for (int r = 0; r < 4; r++) acc[i][j][r] = 0.f;
    uint32_t ahb = smem_u32p(&Ahs[0][0]);
    uint32_t alb = smem_u32p(&Als[0][0]);
    uint32_t bhb = smem_u32p(&Bhs[0][0]);
    uint32_t blb = smem_u32p(&Bls[0][0]);

    // 128 rows x 16 u32 per tile = 512 uint4, 2 per thread
    auto loadT = [&](void* dst, const void* src, int row0, int c) {
        uint4* d4 = (uint4*)dst;
        const uint4* s4 = (const uint4*)src;
        #pragma unroll
        for (int l = 0; l < 2; l++) {
            int f = l*256 + tid; int r = f >> 2, q = f & 3;
            d4[r*5 + q] = s4[(size_t)(row0 + r)*16 + c*4 + q];
        }
    };

    #pragma unroll 1
    for (int c = 0; c < 4; c++) {   // 4 chunks of 32 k
        loadT(Ahs, g_Hh, m0, c);
        loadT(Als, g_Hl, m0, c);
        loadT(Bhs, g_Wch, n0, c);
        loadT(Bls, g_Wcl, n0, c);
        __syncthreads();
        #pragma unroll
        for (int ki = 0; ki < 2; ki++) {
            uint32_t ah[4][4], al[4][4], bh[4][2], bl[4][2];
            #pragma unroll
            for (int mf = 0; mf < 4; mf++) {
                uint32_t off = ((wm*64 + mf*16 + (lane & 15))*40 + ki*16 + (lane >> 4)*8)*2;
                ldsm4(ah[mf][0], ah[mf][1], ah[mf][2], ah[mf][3], ahb + off);
                ldsm4(al[mf][0], al[mf][1], al[mf][2], al[mf][3], alb + off);
            }
            #pragma unroll
            for (int g = 0; g < 2; g++) {
                uint32_t off = ((wn*32 + g*16 + (lane & 15))*40 + ki*16 + (lane >> 4)*8)*2;
                uint32_t r0, r1, r2, r3;
                ldsm4(r0, r1, r2, r3, bhb + off);
                bh[g*2][0] = r0; bh[g*2][1] = r2; bh[g*2+1][0] = r1; bh[g*2+1][1] = r3;
                ldsm4(r0, r1, r2, r3, blb + off);
                bl[g*2][0] = r0; bl[g*2][1] = r2; bl[g*2+1][0] = r1; bl[g*2+1][1] = r3;
            }
            #pragma unroll
            for (int mf = 0; mf < 4; mf++)
                #pragma unroll
                for (int nf = 0; nf < 4; nf++) {
                    mma16816(acc[mf][nf], ah[mf], bh[nf]);
                    mma16816(acc[mf][nf], al[mf], bh[nf]);
                    mma16816(acc[mf][nf], ah[mf], bl[nf]);
                }
        }
        __syncthreads();
    }
    // epilogue
    int seg = blockIdx.x;  // 0:q 1:k 2:A 3:Bp
    #pragma unroll
    for (int mf = 0; mf < 4; mf++)
        #pragma unroll
        for (int nf = 0; nf < 4; nf++)
            #pragma unroll
            for (int r = 0; r < 4; r++) {
                int m = m0 + wm*64 + mf*16 + (lane >> 2) + ((r >> 1) << 3);
                int nl = wn*32 + nf*8 + ((lane & 3) << 1) + (r & 1);
                float v = acc[mf][nf][r];
                int b_ = m >> 14, nn = (m >> 6) & 255, t = m & 63;
                size_t base = (size_t)((b_*TT + t)*NN + nn);
                if (seg == 0) {
                    size_t d = base*DH + nl;
                    split2(v + biasq[nl], g_qh + d, g_ql + d);
                } else if (seg == 1) {
                    size_t d = base*DH + nl;
                    split2(v + biask[nl], g_kh + d, g_kl + d);
                } else if (seg == 2) {
                    g_A[(size_t)m*DD + nl] = v;
                } else {
                    float bpv = v + g_Ej[(size_t)(b_*NN + nn)*DD + nl];
                    size_t d = base*DD + nl;
                    split2(bpv, g_Bph + d, g_Bpl + d);
                }
            }
}

// ---------------- k2m: scores per (b,t): Q @ K^T ----------------
__global__ __launch_bounds__(256) void k2m() {
    __shared__ __align__(16) __nv_bfloat16 Ahs[128][40];
    __shared__ __align__(16) __nv_bfloat16 Als[128][40];
    __shared__ __align__(16) __nv_bfloat16 Bhs[128][40];
    __shared__ __align__(16) __nv_bfloat16 Bls[128][40];
    int tid = threadIdx.x, lane = tid & 31, w = tid >> 5;
    int wm = w & 1, wn = w >> 1;
    int bt = blockIdx.z;
    const int n0 = blockIdx.x * 128;
    const int m0 = blockIdx.y * 128;
    float acc[4][4][4];
    #pragma unroll
    for (int i = 0; i < 4; i++)
        #pragma unroll
        for (int j = 0; j < 4; j++)
            #pragma unroll
            for (int r = 0; r < 4; r++) acc[i][j][r] = 0.f;
    uint32_t ahb = smem_u32p(&Ahs[0][0]);
    uint32_t alb = smem_u32p(&Als[0][0]);
    uint32_t bhb = smem_u32p(&Bhs[0][0]);
    uint32_t blb = smem_u32p(&Bls[0][0]);
    const uint4* qh4 = (const uint4*)g_qh + (size_t)bt*NN*16;
    const uint4* ql4 = (const uint4*)g_ql + (size_t)bt*NN*16;
    const uint4* kh4 = (const uint4*)g_kh + (size_t)bt*NN*16;
    const uint4* kl4 = (const uint4*)g_kl + (size_t)bt*NN*16;

    auto loadT = [&](void* dst, const uint4* s4, int row0, int c) {
        uint4* d4 = (uint4*)dst;
        #pragma unroll
        for (int l = 0; l < 2; l++) {
            int f = l*256 + tid; int r = f >> 2, q = f & 3;
            d4[r*5 + q] = s4[(size_t)(row0 + r)*16 + c*4 + q];
        }
    };

    #pragma unroll 1
    for (int c = 0; c < 4; c++) {
        loadT(Ahs, qh4, m0, c);
        loadT(Als, ql4, m0, c);
        loadT(Bhs, kh4, n0, c);
        loadT(Bls, kl4, n0, c);
        __syncthreads();
        #pragma unroll
        for (int ki = 0; ki < 2; ki++) {
            uint32_t ah[4][4], al[4][4], bh[4][2], bl[4][2];
            #pragma unroll
            for (int mf = 0; mf < 4; mf++) {
                uint32_t off = ((wm*64 + mf*16 + (lane & 15))*40 + ki*16 + (lane >> 4)*8)*2;
                ldsm4(ah[mf][0], ah[mf][1], ah[mf][2], ah[mf][3], ahb + off);
                ldsm4(al[mf][0], al[mf][1], al[mf][2], al[mf][3], alb + off);
            }
            #pragma unroll
            for (int g = 0; g < 2; g++) {
                uint32_t off = ((wn*32 + g*16 + (lane & 15))*40 + ki*16 + (lane >> 4)*8)*2;
                uint32_t r0, r1, r2, r3;
                ldsm4(r0, r1, r2, r3, bhb + off);
                bh[g*2][0] = r0; bh[g*2][1] = r2; bh[g*2+1][0] = r1; bh[g*2+1][1] = r3;
                ldsm4(r0, r1, r2, r3, blb + off);
                bl[g*2][0] = r0; bl[g*2][1] = r2; bl[g*2+1][0] = r1; bl[g*2+1][1] = r3;
            }
            #pragma unroll
            for (int mf = 0; mf < 4; mf++)
                #pragma unroll
                for (int nf = 0; nf < 4; nf++) {
                    mma16816(acc[mf][nf], ah[mf], bh[nf]);
                    mma16816(acc[mf][nf], al[mf], bh[nf]);
                    mma16816(acc[mf][nf], ah[mf], bl[nf]);
                }
        }
        __syncthreads();
    }
    float* C = g_S + (size_t)bt*NN*NN;
    #pragma unroll
    for (int mf = 0; mf < 4; mf++)
        #pragma unroll
        for (int nf = 0; nf < 4; nf++) {
            int m = m0 + wm*64 + mf*16 + (lane >> 2);
            int n = n0 + wn*32 + nf*8 + ((lane & 3) << 1);
            float2 v0 = make_float2(acc[mf][nf][0], acc[mf][nf][1]);
            float2 v1 = make_float2(acc[mf][nf][2], acc[mf][nf][3]);
            *(float2*)&C[(size_t)m*NN + n] = v0;
            *(float2*)&C[(size_t)(m + 8)*NN + n] = v1;
        }
}

// ---------------- ksoft: add R-term, softmax over t, mask, write w (no wsum here) ----------------
__global__ __launch_bounds__(256) void ksoft(const float* __restrict__ R) {
    int bi = blockIdx.x; int b = bi >> 8, i = bi & 255;
    int j = threadIdx.x;
    __shared__ float Ps[TT][DR];
    __shared__ float qbrs[TT];
    #pragma unroll
    for (int l = 0; l < 8; l++) {
        int f = l*256 + j; int t = f >> 5, r = f & 31;
        Ps[t][r] = g_P[((size_t)bi*TT + t)*DR + r];
    }
    if (j < TT) qbrs[j] = g_qbr[(size_t)bi*TT + j];
    __syncthreads();
    float Rr[DR];
    const float* Rp = R + ((size_t)bi*NN + j)*DR;
    #pragma unroll
    for (int r4 = 0; r4 < 8; r4++) {
        float4 v = *(const float4*)(Rp + r4*4);
        Rr[r4*4+0] = v.x; Rr[r4*4+1] = v.y; Rr[r4*4+2] = v.z; Rr[r4*4+3] = v.w;
    }
    float sv[TT];
    const float rs = 0.08838834764831845f;  // 1/sqrt(128)
    size_t sbase = ((size_t)b*TT*NN + i)*NN + j;
    #pragma unroll
    for (int t = 0; t < TT; t++) {
        float qk = g_S[sbase + (size_t)t*NN*NN];
        float rt = 0.f;
        #pragma unroll
        for (int r = 0; r < DR; r++) rt += Ps[t][r]*Rr[r];
        sv[t] = (qk + rt + qbrs[t])*rs;
    }
    float mx = sv[0];
    #pragma unroll
    for (int t = 1; t < TT; t++) mx = fmaxf(mx, sv[t]);
    float sum = 0.f;
    #pragma unroll
    for (int t = 0; t < TT; t++) { sv[t] = __expf(sv[t]-mx); sum += sv[t]; }
    float inv = (j == i) ? 0.f : (1.f/sum);
    #pragma unroll
    for (int t = 0; t < TT; t++) {
        float wv = sv[t]*inv;
        size_t idx = sbase + (size_t)t*NN*NN;
        split2(wv, g_wh + idx, g_wl + idx);
    }
}

// ---------------- kp: P = H @ WQR + brq ; qbr = H @ wqbr + c0 ----------------
__global__ __launch_bounds__(256) void kp_P(const float* __restrict__ H) {
    int bi = blockIdx.x;
    __shared__ float Hs[TT][33];
    __shared__ float Ws[32][DR];
    __shared__ float wqbrs[32];
    int tid = threadIdx.x;
    int t = tid >> 2, rg = (tid & 3)*8;
    float acc[8];
    #pragma unroll
    for (int r = 0; r < 8; r++) acc[r] = 0.f;
    float qacc = 0.f;
    const float* Hbase = H + (size_t)bi*TT*DD;
    for (int d0 = 0; d0 < DD; d0 += 32) {
        #pragma unroll
        for (int l = 0; l < 8; l++) {
            int f = l*256 + tid; int t2 = f >> 5, dd = f & 31;
            Hs[t2][dd] = Hbase[t2*DD + d0 + dd];
        }
        #pragma unroll
        for (int l = 0; l < 4; l++) {
            int f = l*256 + tid; int dd = f >> 5, r = f & 31;
            Ws[dd][r] = g_WQR[(d0 + dd)*DR + r];
        }
        if (tid < 32) wqbrs[tid] = g_wqbr[d0 + tid];
        __syncthreads();
        #pragma unroll
        for (int dd = 0; dd < 32; dd++) {
            float a = Hs[t][dd];
            #pragma unroll
            for (int rr = 0; rr < 8; rr++) acc[rr] += a * Ws[dd][rg + rr];
            qacc += a * wqbrs[dd];
        }
        __syncthreads();
    }
    size_t pb = ((size_t)bi*TT + t)*DR + rg;
    #pragma unroll
    for (int rr = 0; rr < 8; rr++) g_P[pb + rr] = acc[rr] + g_brq[rg + rr];
    if (rg == 0) g_qbr[(size_t)bi*TT + t] = qacc + g_c0;
}

// ---------------- kwr: WR = sum_j w*R, wsum = sum_j w (w = wh+wl) ----------------
__global__ __launch_bounds__(256) void kwr(const float* __restrict__ R) {
    int bi = blockIdx.x; int b = bi >> 8, i = bi & 255;
    __shared__ float Rs[32][33];
    __shared__ float wsm[TT][33];
    int tid = threadIdx.x;
    int t = tid >> 2, rg = (tid & 3)*8;
    float acc[8];
    #pragma unroll
    for (int r = 0; r < 8; r++) acc[r] = 0.f;
    float wsacc = 0.f;
    for (int j0 = 0; j0 < NN; j0 += 32) {
        #pragma unroll
        for (int l = 0; l < 4; l++) {
            int f = l*256 + tid; int jj = f >> 5, r = f & 31;
            Rs[jj][r] = R[((size_t)bi*NN + j0 + jj)*DR + r];
        }
        // w reconstruct: 64 t x 16 bf162 pairs = 1024 pairs, 4 per thread
        #pragma unroll
        for (int l = 0; l < 4; l++) {
            int f = l*256 + tid; int t2 = f >> 4, jp = f & 15;
            size_t idx = ((size_t)(b*TT + t2)*NN + i)*NN + j0 + jp*2;
            __nv_bfloat162 hh = *(const __nv_bfloat162*)&g_wh[idx];
            __nv_bfloat162 ll = *(const __nv_bfloat162*)&g_wl[idx];
            wsm[t2][jp*2]     = __low2float(hh)  + __low2float(ll);
            wsm[t2][jp*2 + 1] = __high2float(hh) + __high2float(ll);
        }
        __syncthreads();
        #pragma unroll
        for (int jj = 0; jj < 32; jj++) {
            float wv = wsm[t][jj];
            wsacc += wv;
            #pragma unroll
            for (int rr = 0; rr < 8; rr++) acc[rr] += wv * Rs[jj][rg + rr];
        }
        __syncthreads();
    }
    size_t ob = ((size_t)bi*TT + t)*DR + rg;
    #pragma unroll
    for (int rr = 0; rr < 8; rr++) g_WR[ob + rr] = acc[rr];
    if (rg == 0) g_wsum[(size_t)bi*TT + t] = wsacc;
}

// ---------------- k3m: z2 per (b,t): w @ Bp ----------------
__global__ __launch_bounds__(256) void k3m() {
    __shared__ __align__(16) __nv_bfloat16 Ahs[128][40];  // w hi: 128 i x 32 j
    __shared__ __align__(16) __nv_bfloat16 Als[128][40];  // w lo
    __shared__ __align__(16) __nv_bfloat16 Bhs[32][136];  // Bp hi: 32 j x 128 e
    __shared__ __align__(16) __nv_bfloat16 Bls[32][136];  // Bp lo
    int tid = threadIdx.x, lane = tid & 31, w = tid >> 5;
    int wm = w & 1, wn = w >> 1;
    int bt = blockIdx.z;
    const int m0 = blockIdx.y * 128;
    float acc[4][4][4];
    #pragma unroll
    for (int i = 0; i < 4; i++)
        #pragma unroll
        for (int j = 0; j < 4; j++)
            #pragma unroll
            for (int r = 0; r < 4; r++) acc[i][j][r] = 0.f;
    uint32_t ahb = smem_u32p(&Ahs[0][0]);
    uint32_t alb = smem_u32p(&Als[0][0]);
    uint32_t bhb = smem_u32p(&Bhs[0][0]);
    uint32_t blb = smem_u32p(&Bls[0][0]);
    const uint4* wh4  = (const uint4*)g_wh  + (size_t)bt*NN*32;
    const uint4* wl4  = (const uint4*)g_wl  + (size_t)bt*NN*32;
    const uint4* bph4 = (const uint4*)g_Bph + (size_t)bt*NN*16;
    const uint4* bpl4 = (const uint4*)g_Bpl + (size_t)bt*NN*16;

    // A: 128 rows x 4 uint4 (32 bf16), 512 uint4 total
    auto loadA = [&](void* dst, const uint4* s4, int c) {
        uint4* d4 = (uint4*)dst;
        #pragma unroll
        for (int l = 0; l < 2; l++) {
            int f = l*256 + tid; int r = f >> 2, q = f & 3;
            d4[r*5 + q] = s4[(size_t)(m0 + r)*32 + c*4 + q];
        }
    };
    // B: 32 rows x 16 uint4 (128 bf16), 512 uint4 total
    auto loadB = [&](void* dst, const uint4* s4, int c) {
        uint4* d4 = (uint4*)dst;
        #pragma unroll
        for (int l = 0; l < 2; l++) {
            int f = l*256 + tid; int r = f >> 4, q = f & 15;
            d4[r*17 + q] = s4[(size_t)(c*32 + r)*16 + q];
        }
    };

    #pragma unroll 1
    for (int c = 0; c < 8; c++) {   // K=256 in chunks of 32
        loadA(Ahs, wh4, c);
        loadA(Als, wl4, c);
        loadB(Bhs, bph4, c);
        loadB(Bls, bpl4, c);
        __syncthreads();
        #pragma unroll
        for (int ki = 0; ki < 2; ki++) {
            uint32_t ah[4][4], al[4][4], bh[4][2], bl[4][2];
            #pragma unroll
            for (int mf = 0; mf < 4; mf++) {
                uint32_t off = ((wm*64 + mf*16 + (lane & 15))*40 + ki*16 + (lane >> 4)*8)*2;
                ldsm4(ah[mf][0], ah[mf][1], ah[mf][2], ah[mf][3], ahb + off);
                ldsm4(al[mf][0], al[mf][1], al[mf][2], al[mf][3], alb + off);
            }
            #pragma unroll
            for (int g = 0; g < 2; g++) {
                uint32_t off = ((ki*16 + (lane & 15))*136 + wn*32 + g*16 + (lane >> 4)*8)*2;
                uint32_t r0, r1, r2, r3;
                ldsm4t(r0, r1, r2, r3, bhb + off);
                bh[g*2][0] = r0; bh[g*2][1] = r1; bh[g*2+1][0] = r2; bh[g*2+1][1] = r3;
                ldsm4t(r0, r1, r2, r3, blb + off);
                bl[g*2][0] = r0; bl[g*2][1] = r1; bl[g*2+1][0] = r2; bl[g*2+1][1] = r3;
            }
            #pragma unroll
            for (int mf = 0; mf < 4; mf++)
                #pragma unroll
                for (int nf = 0; nf < 4; nf++) {
                    mma16816(acc[mf][nf], ah[mf], bh[nf]);
                    mma16816(acc[mf][nf], al[mf], bh[nf]);
                    mma16816(acc[mf][nf], ah[mf], bl[nf]);
                }
        }
        __syncthreads();
    }
    float* C = g_Z2 + (size_t)bt*NN*DD;
    #pragma unroll
    for (int mf = 0; mf < 4; mf++)
        #pragma unroll
        for (int nf = 0; nf < 4; nf++) {
            int m = m0 + wm*64 + mf*16 + (lane >> 2);
            int n = wn*32 + nf*8 + ((lane & 3) << 1);
            float2 v0 = make_float2(acc[mf][nf][0], acc[mf][nf][1]);
            float2 v1 = make_float2(acc[mf][nf][2], acc[mf][nf][3]);
            *(float2*)&C[(size_t)m*DD + n] = v0;
            *(float2*)&C[(size_t)(m + 8)*DD + n] = v1;
        }
}

// ---------------- kfin: warp-per-row z assembly + residual + LayerNorm ----------------
__global__ __launch_bounds__(256) void kfin(const float* __restrict__ H,
                                            const float* __restrict__ Wf,
                                            const float* __restrict__ bf,
                                            const float* __restrict__ gamma,
                                            const float* __restrict__ beta,
                                            float* __restrict__ out) {
    int bi = blockIdx.x; int b = bi >> 8, i = bi & 255;
    __shared__ float W3s[DD][33];
    __shared__ float WRs[TT][DR];
    __shared__ float wsums[TT];
    __shared__ float bfs[DD], gs[DD], bts[DD];
    int tid = threadIdx.x;
    #pragma unroll
    for (int l = 0; l < 16; l++) {
        int f = l*256 + tid; int e = f >> 5, r = f & 31;
        W3s[e][r] = Wf[e*WF_LD + 2*DD + r];
    }
    #pragma unroll
    for (int l = 0; l < 8; l++) {
        int f = l*256 + tid; int t = f >> 5, r = f & 31;
        WRs[t][r] = g_WR[((size_t)bi*TT + t)*DR + r];
    }
    if (tid < TT) wsums[tid] = g_wsum[(size_t)bi*TT + tid];
    if (tid < DD) { bfs[tid] = bf[tid]; gs[tid] = gamma[tid]; bts[tid] = beta[tid]; }
    __syncthreads();
    int lane = tid & 31, w = tid >> 5;
    #pragma unroll 1
    for (int pass = 0; pass < 8; pass++) {
        int t = pass*8 + w;
        size_t rowH = ((size_t)bi*TT + t)*DD;
        size_t rowZ = ((size_t)(b*TT + t)*NN + i)*DD;
        float wst = wsums[t];
        float z3[4];
        #pragma unroll
        for (int k = 0; k < 4; k++) z3[k] = 0.f;
        #pragma unroll
        for (int r = 0; r < DR; r++) {
            float wr = WRs[t][r];
            #pragma unroll
            for (int k = 0; k < 4; k++) z3[k] += wr * W3s[lane + 32*k][r];
        }
        float v[4], s1 = 0.f, s2 = 0.f;
        #pragma unroll
        for (int k = 0; k < 4; k++) {
            int e = lane + 32*k;
            float x = H[rowH + e] + (g_A[rowH + e] + bfs[e])*wst + g_Z2[rowZ + e] + z3[k];
            v[k] = x; s1 += x; s2 += x*x;
        }
        #pragma unroll
        for (int o = 16; o; o >>= 1) {
            s1 += __shfl_xor_sync(0xffffffffu, s1, o);
            s2 += __shfl_xor_sync(0xffffffffu, s2, o);
        }
        float mu = s1*(1.f/128.f);
        float var = s2*(1.f/128.f) - mu*mu;
        float isd = rsqrtf(var + 1e-5f);
        #pragma unroll
        for (int k = 0; k < 4; k++) {
            int e = lane + 32*k;
            out[rowH + e] = (v[k] - mu)*isd*gs[e] + bts[e];
        }
    }
}

// ---------------- launch ----------------
extern "C" void kernel_launch(void* const* d_in, const int* in_sizes, int n_in,
                              void* d_out, int out_size) {
    const float* H      = (const float*)d_in[0];
    const float* R      = (const float*)d_in[1];
    const float* deltaH = (const float*)d_in[2];
    const float* Wq     = (const float*)d_in[3];
    const float* bq     = (const float*)d_in[4];
    const float* Wk     = (const float*)d_in[5];
    const float* bk     = (const float*)d_in[6];
    const float* Wr     = (const float*)d_in[7];
    const float* br     = (const float*)d_in[8];
    const float* Wf     = (const float*)d_in[9];
    const float* bf     = (const float*)d_in[10];
    const float* gamma  = (const float*)d_in[11];
    const float* beta   = (const float*)d_in[12];
    float* out = (float*)d_out;

    kprep<<<1, 128>>>(Wq, bq, Wr, br);
    kw_build<<<256, 256>>>(Wq, Wk, Wf);
    kw4t<<<64, 256>>>(Wf);
    kconv_H<<<8192, 256>>>(H);
    k0a<<<BB*NN, 256>>>(deltaH);
    k0b<<<64, 256>>>();
    k1m<<<dim3(4, 512), 256>>>(bq, bk);
    kp_P<<<BB*NN, 256>>>(H);
    k2m<<<dim3(2, 2, BB*TT), 256>>>();
    ksoft<<<BB*NN, 256>>>(R);
    kwr<<<BB*NN, 256>>>(R);
    k3m<<<dim3(1, 2, BB*TT), 256>>>();
    kfin<<<BB*NN, 256>>>(H, Wf, bf, gamma, beta, out);
}

// round 12
// speedup vs baseline: 1.3024x; 1.0494x over previous
#include <cuda_runtime.h>
#include <cuda_bf16.h>
#include <math.h>
#include <stdint.h>

#define BB 4
#define NN 256
#define TT 64
#define DD 128
#define DR 32
#define DH 128
#define WF_LD (3*DD+DR)   // 416

// ---------------- device scratch ----------------
__device__ float g_A   [(size_t)BB*NN*TT*DD];   // (b,n,t,e)
__device__ float g_S   [(size_t)BB*TT*NN*NN];   // (b,t,i,j) scores
__device__ float g_Z2  [(size_t)BB*TT*NN*DD];   // (b,t,i,e)
__device__ float g_P   [BB*NN*TT*DR];   // (b,i,t,r)
__device__ float g_qbr [BB*NN*TT];
__device__ float g_wsum[BB*NN*TT];      // (b,i,t)
__device__ float g_WR  [BB*NN*TT*DR];   // (b,i,t,r)
__device__ float g_Ej  [BB*NN*DD];      // (b,j,e)
__device__ float g_dsum[BB*NN*DD];
__device__ float g_W4t [DD*DD];         // [dd][e]
__device__ float g_WQR [DD*DR];
__device__ float g_brq [DR];
__device__ float g_wqbr[DD];
__device__ float g_c0;

// bf16 split operands (128B aligned for uint4 access)
__device__ __align__(128) __nv_bfloat16 g_Hh [(size_t)BB*NN*TT*DD];
__device__ __align__(128) __nv_bfloat16 g_Hl [(size_t)BB*NN*TT*DD];
__device__ __align__(128) __nv_bfloat16 g_Wch[4*DH*DD];
__device__ __align__(128) __nv_bfloat16 g_Wcl[4*DH*DD];
__device__ __align__(128) __nv_bfloat16 g_qh [(size_t)BB*TT*NN*DH];
__device__ __align__(128) __nv_bfloat16 g_ql [(size_t)BB*TT*NN*DH];
__device__ __align__(128) __nv_bfloat16 g_kh [(size_t)BB*TT*NN*DH];
__device__ __align__(128) __nv_bfloat16 g_kl [(size_t)BB*TT*NN*DH];
__device__ __align__(128) __nv_bfloat16 g_Bph[(size_t)BB*TT*NN*DD];
__device__ __align__(128) __nv_bfloat16 g_Bpl[(size_t)BB*TT*NN*DD];
__device__ __align__(128) __nv_bfloat16 g_wh [(size_t)BB*TT*NN*NN];
__device__ __align__(128) __nv_bfloat16 g_wl [(size_t)BB*TT*NN*NN];

// ---------------- helpers ----------------
__device__ __forceinline__ void split2(float x, __nv_bfloat16* ph, __nv_bfloat16* pl) {
    __nv_bfloat16 h = __float2bfloat16(x);
    *ph = h;
    *pl = __float2bfloat16(x - __bfloat162float(h));
}
__device__ __forceinline__ uint32_t smem_u32p(const void* p) {
    return (uint32_t)__cvta_generic_to_shared(p);
}
__device__ __forceinline__ void ldsm4(uint32_t& r0, uint32_t& r1, uint32_t& r2, uint32_t& r3, uint32_t a) {
    asm volatile("ldmatrix.sync.aligned.m8n8.x4.shared.b16 {%0,%1,%2,%3}, [%4];"
                 : "=r"(r0), "=r"(r1), "=r"(r2), "=r"(r3) : "r"(a));
}
__device__ __forceinline__ void ldsm4t(uint32_t& r0, uint32_t& r1, uint32_t& r2, uint32_t& r3, uint32_t a) {
    asm volatile("ldmatrix.sync.aligned.m8n8.x4.trans.shared.b16 {%0,%1,%2,%3}, [%4];"
                 : "=r"(r0), "=r"(r1), "=r"(r2), "=r"(r3) : "r"(a));
}
__device__ __forceinline__ void mma16816(float* c, const uint32_t* a, const uint32_t* b) {
    asm volatile("mma.sync.aligned.m16n8k16.row.col.f32.bf16.bf16.f32 "
                 "{%0,%1,%2,%3},{%4,%5,%6,%7},{%8,%9},{%0,%1,%2,%3};"
                 : "+f"(c[0]), "+f"(c[1]), "+f"(c[2]), "+f"(c[3])
                 : "r"(a[0]), "r"(a[1]), "r"(a[2]), "r"(a[3]), "r"(b[0]), "r"(b[1]));
}
__device__ __forceinline__ void cpa16(uint32_t dst, const void* src) {
    asm volatile("cp.async.cg.shared.global [%0], [%1], 16;" :: "r"(dst), "l"(src));
}
#define CP_COMMIT() asm volatile("cp.async.commit_group;")
#define CP_WAIT1()  asm volatile("cp.async.wait_group 1;")
#define CP_WAIT0()  asm volatile("cp.async.wait_group 0;")

// ---------------- kprep: fold Wq into Wr path ----------------
__global__ void kprep(const float* __restrict__ Wq, const float* __restrict__ bq,
                      const float* __restrict__ Wr, const float* __restrict__ br) {
    int d = threadIdx.x; // 128
    float acc[DR];
    #pragma unroll
    for (int r = 0; r < DR; r++) acc[r] = 0.f;
    float wq_br = 0.f;
    for (int h = 0; h < DH; h++) {
        float a = Wq[h*DD + d];
        wq_br += a * br[h];
        #pragma unroll
        for (int r = 0; r < DR; r++) acc[r] += a * Wr[h*DR + r];
    }
    #pragma unroll
    for (int r = 0; r < DR; r++) g_WQR[d*DR + r] = acc[r];
    g_wqbr[d] = wq_br;
    if (d < DR) {
        float s = 0.f;
        for (int h = 0; h < DH; h++) s += bq[h] * Wr[h*DR + d];
        g_brq[d] = s;
    }
    if (d == 0) {
        float s = 0.f;
        for (int h = 0; h < DH; h++) s += bq[h] * br[h];
        g_c0 = s;
    }
}

// ---------------- kw: build concatenated weights + transposed W4 ----------------
__global__ void kw_build(const float* __restrict__ Wq, const float* __restrict__ Wk,
                         const float* __restrict__ Wf) {
    int idx = blockIdx.x*blockDim.x + threadIdx.x;
    if (idx >= 4*DH*DD) return;
    int r = idx / DD, c = idx - r*DD;
    float v;
    if      (r < DH)   v = Wq[r*DD + c];
    else if (r < 2*DH) v = Wk[(r-DH)*DD + c];
    else if (r < 3*DH) v = Wf[(r-2*DH)*WF_LD + c];          // W1
    else               v = Wf[(r-3*DH)*WF_LD + DD + c];     // W2
    split2(v, &g_Wch[idx], &g_Wcl[idx]);
}

__global__ void kw4t(const float* __restrict__ Wf) {
    int f = blockIdx.x*256 + threadIdx.x;   // 16384
    int e = f >> 7, dd = f & 127;
    g_W4t[dd*DD + e] = Wf[e*WF_LD + 2*DD + DR + dd];
}

// ---------------- kconv_H: H fp32 -> bf16 hi/lo (float4) ----------------
__global__ void kconv_H(const float* __restrict__ H) {
    int i = blockIdx.x*blockDim.x + threadIdx.x;   // float4 index
    float4 x = ((const float4*)H)[i];
    __nv_bfloat16 h0,l0,h1,l1,h2,l2,h3,l3;
    split2(x.x,&h0,&l0); split2(x.y,&h1,&l1); split2(x.z,&h2,&l2); split2(x.w,&h3,&l3);
    __nv_bfloat162* ph = (__nv_bfloat162*)g_Hh;
    __nv_bfloat162* pl = (__nv_bfloat162*)g_Hl;
    ph[i*2]   = __nv_bfloat162{h0,h1};
    ph[i*2+1] = __nv_bfloat162{h2,h3};
    pl[i*2]   = __nv_bfloat162{l0,l1};
    pl[i*2+1] = __nv_bfloat162{l2,l3};
}

// ---------------- k0a: dsum[b,j,d] = sum_t dH[b,j,t,d] ----------------
__global__ __launch_bounds__(256) void k0a(const float* __restrict__ dH) {
    int bj = blockIdx.x;
    int tid = threadIdx.x;
    int d4 = tid & 31;
    int ts = tid >> 5;
    const float4* p = (const float4*)(dH + (size_t)bj*TT*DD) + d4;
    float4 s = make_float4(0.f,0.f,0.f,0.f);
    #pragma unroll
    for (int t = ts; t < TT; t += 8) {
        float4 v = p[t*32];
        s.x += v.x; s.y += v.y; s.z += v.z; s.w += v.w;
    }
    __shared__ float4 red[8][32];
    red[ts][d4] = s;
    __syncthreads();
    if (ts == 0) {
        float4 a = red[0][d4];
        #pragma unroll
        for (int k = 1; k < 8; k++) {
            float4 b = red[k][d4];
            a.x += b.x; a.y += b.y; a.z += b.z; a.w += b.w;
        }
        ((float4*)(g_dsum + (size_t)bj*DD))[d4] = a;
    }
}

// ---------------- k0b: Ej = dsum @ W4^T (via W4t) ----------------
__global__ __launch_bounds__(256) void k0b() {
    int r0 = blockIdx.x * 16;
    __shared__ float ds[16][DD];
    int tid = threadIdx.x;
    #pragma unroll
    for (int l = 0; l < 8; l++) {
        int f = l*256 + tid;
        ds[f >> 7][f & 127] = g_dsum[(size_t)(r0 + (f >> 7))*DD + (f & 127)];
    }
    __syncthreads();
    int e = tid & 127, rh = tid >> 7;
    float acc[8];
    #pragma unroll
    for (int rr = 0; rr < 8; rr++) acc[rr] = 0.f;
    for (int dd = 0; dd < DD; dd++) {
        float wv = g_W4t[dd*DD + e];
        #pragma unroll
        for (int rr = 0; rr < 8; rr++) acc[rr] += ds[rh*8 + rr][dd]*wv;
    }
    #pragma unroll
    for (int rr = 0; rr < 8; rr++)
        g_Ej[(size_t)(r0 + rh*8 + rr)*DD + e] = acc[rr];
}

// ======= split-GEMM core: resident hi/lo tiles + cp.async double buffering =======
// k1m/k2m stage: Ah(10240) Al(10240) Bh(10240) Bl(10240) = 40960 B; 2 stages = 81920.

// ---------------- k1m: fused projection GEMM ----------------
__global__ __launch_bounds__(256) void k1m(const float* __restrict__ bq,
                                           const float* __restrict__ bk) {
    extern __shared__ __align__(128) char dyns[];
    __shared__ float biasq[DH], biask[DH];
    int tid = threadIdx.x, lane = tid & 31, w = tid >> 5;
    int wm = w & 1, wn = w >> 1;
    if (tid < DH) { biasq[tid] = bq[tid]; biask[tid] = bk[tid]; }
    const int n0 = blockIdx.x * 128;
    const int m0 = blockIdx.y * 128;
    uint32_t sb = smem_u32p(dyns);
    float acc[4][4][4];
    #pragma unroll
    for (int i = 0; i < 4; i++)
        #pragma unroll
        for (int j = 0; j < 4; j++)
            #pragma unroll
            for (int r = 0; r < 4; r++) acc[i][j][r] = 0.f;
    const uint4* Ah4 = (const uint4*)g_Hh;
    const uint4* Al4 = (const uint4*)g_Hl;
    const uint4* Bh4 = (const uint4*)g_Wch;
    const uint4* Bl4 = (const uint4*)g_Wcl;

    auto loadT = [&](uint32_t dst, const uint4* s4, int row0, int c) {
        #pragma unroll
        for (int l = 0; l < 2; l++) {
            int f = l*256 + tid; int r = f >> 2, q = f & 3;
            cpa16(dst + (uint32_t)(r*80 + q*16), s4 + (size_t)(row0 + r)*16 + c*4 + q);
        }
    };
    auto prefetch = [&](int stage, int c) {
        uint32_t s0 = sb + stage*40960;
        loadT(s0,         Ah4, m0, c);
        loadT(s0 + 10240, Al4, m0, c);
        loadT(s0 + 20480, Bh4, n0, c);
        loadT(s0 + 30720, Bl4, n0, c);
        CP_COMMIT();
    };

    prefetch(0, 0);
    #pragma unroll 1
    for (int c = 0; c < 4; c++) {
        int cur = c & 1;
        if (c < 3) { prefetch(cur ^ 1, c + 1); CP_WAIT1(); }
        else       { CP_WAIT0(); }
        __syncthreads();
        uint32_t ahb = sb + cur*40960, alb = ahb + 10240, bhb = ahb + 20480, blb = ahb + 30720;
        #pragma unroll
        for (int ki = 0; ki < 2; ki++) {
            uint32_t ah[4][4], al[4][4], bh[4][2], bl[4][2];
            #pragma unroll
            for (int mf = 0; mf < 4; mf++) {
                uint32_t off = ((wm*64 + mf*16 + (lane & 15))*40 + ki*16 + (lane >> 4)*8)*2;
                ldsm4(ah[mf][0], ah[mf][1], ah[mf][2], ah[mf][3], ahb + off);
                ldsm4(al[mf][0], al[mf][1], al[mf][2], al[mf][3], alb + off);
            }
            #pragma unroll
            for (int g = 0; g < 2; g++) {
                uint32_t off = ((wn*32 + g*16 + (lane & 15))*40 + ki*16 + (lane >> 4)*8)*2;
                uint32_t r0, r1, r2, r3;
                ldsm4(r0, r1, r2, r3, bhb + off);
                bh[g*2][0] = r0; bh[g*2][1] = r2; bh[g*2+1][0] = r1; bh[g*2+1][1] = r3;
                ldsm4(r0, r1, r2, r3, blb + off);
                bl[g*2][0] = r0; bl[g*2][1] = r2; bl[g*2+1][0] = r1; bl[g*2+1][1] = r3;
            }
            #pragma unroll
            for (int mf = 0; mf < 4; mf++)
                #pragma unroll
                for (int nf = 0; nf < 4; nf++) {
                    mma16816(acc[mf][nf], ah[mf], bh[nf]);
                    mma16816(acc[mf][nf], al[mf], bh[nf]);
                    mma16816(acc[mf][nf], ah[mf], bl[nf]);
                }
        }
        __syncthreads();
    }
    // epilogue
    int seg = blockIdx.x;  // 0:q 1:k 2:A 3:Bp
    #pragma unroll
    for (int mf = 0; mf < 4; mf++)
        #pragma unroll
        for (int nf = 0; nf < 4; nf++)
            #pragma unroll
            for (int r = 0; r < 4; r++) {
                int m = m0 + wm*64 + mf*16 + (lane >> 2) + ((r >> 1) << 3);
                int nl = wn*32 + nf*8 + ((lane & 3) << 1) + (r & 1);
                float v = acc[mf][nf][r];
                int b_ = m >> 14, nn = (m >> 6) & 255, t = m & 63;
                size_t base = (size_t)((b_*TT + t)*NN + nn);
                if (seg == 0) {
                    size_t d = base*DH + nl;
                    split2(v + biasq[nl], g_qh + d, g_ql + d);
                } else if (seg == 1) {
                    size_t d = base*DH + nl;
                    split2(v + biask[nl], g_kh + d, g_kl + d);
                } else if (seg == 2) {
                    g_A[(size_t)m*DD + nl] = v;
                } else {
                    float bpv = v + g_Ej[(size_t)(b_*NN + nn)*DD + nl];
                    size_t d = base*DD + nl;
                    split2(bpv, g_Bph + d, g_Bpl + d);
                }
            }
}

// ---------------- k2m: scores per (b,t): Q @ K^T ----------------
__global__ __launch_bounds__(256) void k2m() {
    extern __shared__ __align__(128) char dyns[];
    int tid = threadIdx.x, lane = tid & 31, w = tid >> 5;
    int wm = w & 1, wn = w >> 1;
    int bt = blockIdx.z;
    const int n0 = blockIdx.x * 128;
    const int m0 = blockIdx.y * 128;
    uint32_t sb = smem_u32p(dyns);
    float acc[4][4][4];
    #pragma unroll
    for (int i = 0; i < 4; i++)
        #pragma unroll
        for (int j = 0; j < 4; j++)
            #pragma unroll
            for (int r = 0; r < 4; r++) acc[i][j][r] = 0.f;
    const uint4* qh4 = (const uint4*)g_qh + (size_t)bt*NN*16;
    const uint4* ql4 = (const uint4*)g_ql + (size_t)bt*NN*16;
    const uint4* kh4 = (const uint4*)g_kh + (size_t)bt*NN*16;
    const uint4* kl4 = (const uint4*)g_kl + (size_t)bt*NN*16;

    auto loadT = [&](uint32_t dst, const uint4* s4, int row0, int c) {
        #pragma unroll
        for (int l = 0; l < 2; l++) {
            int f = l*256 + tid; int r = f >> 2, q = f & 3;
            cpa16(dst + (uint32_t)(r*80 + q*16), s4 + (size_t)(row0 + r)*16 + c*4 + q);
        }
    };
    auto prefetch = [&](int stage, int c) {
        uint32_t s0 = sb + stage*40960;
        loadT(s0,         qh4, m0, c);
        loadT(s0 + 10240, ql4, m0, c);
        loadT(s0 + 20480, kh4, n0, c);
        loadT(s0 + 30720, kl4, n0, c);
        CP_COMMIT();
    };

    prefetch(0, 0);
    #pragma unroll 1
    for (int c = 0; c < 4; c++) {
        int cur = c & 1;
        if (c < 3) { prefetch(cur ^ 1, c + 1); CP_WAIT1(); }
        else       { CP_WAIT0(); }
        __syncthreads();
        uint32_t ahb = sb + cur*40960, alb = ahb + 10240, bhb = ahb + 20480, blb = ahb + 30720;
        #pragma unroll
        for (int ki = 0; ki < 2; ki++) {
            uint32_t ah[4][4], al[4][4], bh[4][2], bl[4][2];
            #pragma unroll
            for (int mf = 0; mf < 4; mf++) {
                uint32_t off = ((wm*64 + mf*16 + (lane & 15))*40 + ki*16 + (lane >> 4)*8)*2;
                ldsm4(ah[mf][0], ah[mf][1], ah[mf][2], ah[mf][3], ahb + off);
                ldsm4(al[mf][0], al[mf][1], al[mf][2], al[mf][3], alb + off);
            }
            #pragma unroll
            for (int g = 0; g < 2; g++) {
                uint32_t off = ((wn*32 + g*16 + (lane & 15))*40 + ki*16 + (lane >> 4)*8)*2;
                uint32_t r0, r1, r2, r3;
                ldsm4(r0, r1, r2, r3, bhb + off);
                bh[g*2][0] = r0; bh[g*2][1] = r2; bh[g*2+1][0] = r1; bh[g*2+1][1] = r3;
                ldsm4(r0, r1, r2, r3, blb + off);
                bl[g*2][0] = r0; bl[g*2][1] = r2; bl[g*2+1][0] = r1; bl[g*2+1][1] = r3;
            }
            #pragma unroll
            for (int mf = 0; mf < 4; mf++)
                #pragma unroll
                for (int nf = 0; nf < 4; nf++) {
                    mma16816(acc[mf][nf], ah[mf], bh[nf]);
                    mma16816(acc[mf][nf], al[mf], bh[nf]);
                    mma16816(acc[mf][nf], ah[mf], bl[nf]);
                }
        }
        __syncthreads();
    }
    float* C = g_S + (size_t)bt*NN*NN;
    #pragma unroll
    for (int mf = 0; mf < 4; mf++)
        #pragma unroll
        for (int nf = 0; nf < 4; nf++) {
            int m = m0 + wm*64 + mf*16 + (lane >> 2);
            int n = n0 + wn*32 + nf*8 + ((lane & 3) << 1);
            float2 v0 = make_float2(acc[mf][nf][0], acc[mf][nf][1]);
            float2 v1 = make_float2(acc[mf][nf][2], acc[mf][nf][3]);
            *(float2*)&C[(size_t)m*NN + n] = v0;
            *(float2*)&C[(size_t)(m + 8)*NN + n] = v1;
        }
}

// ---------------- ksoft: add R-term, softmax over t, mask, write w ----------------
__global__ __launch_bounds__(256) void ksoft(const float* __restrict__ R) {
    int bi = blockIdx.x; int b = bi >> 8, i = bi & 255;
    int j = threadIdx.x;
    __shared__ float Ps[TT][DR];
    __shared__ float qbrs[TT];
    #pragma unroll
    for (int l = 0; l < 8; l++) {
        int f = l*256 + j; int t = f >> 5, r = f & 31;
        Ps[t][r] = g_P[((size_t)bi*TT + t)*DR + r];
    }
    if (j < TT) qbrs[j] = g_qbr[(size_t)bi*TT + j];
    __syncthreads();
    float Rr[DR];
    const float* Rp = R + ((size_t)bi*NN + j)*DR;
    #pragma unroll
    for (int r4 = 0; r4 < 8; r4++) {
        float4 v = *(const float4*)(Rp + r4*4);
        Rr[r4*4+0] = v.x; Rr[r4*4+1] = v.y; Rr[r4*4+2] = v.z; Rr[r4*4+3] = v.w;
    }
    float sv[TT];
    const float rs = 0.08838834764831845f;  // 1/sqrt(128)
    size_t sbase = ((size_t)b*TT*NN + i)*NN + j;
    #pragma unroll
    for (int t = 0; t < TT; t++) {
        float qk = g_S[sbase + (size_t)t*NN*NN];
        float rt = 0.f;
        #pragma unroll
        for (int r = 0; r < DR; r++) rt += Ps[t][r]*Rr[r];
        sv[t] = (qk + rt + qbrs[t])*rs;
    }
    float mx = sv[0];
    #pragma unroll
    for (int t = 1; t < TT; t++) mx = fmaxf(mx, sv[t]);
    float sum = 0.f;
    #pragma unroll
    for (int t = 0; t < TT; t++) { sv[t] = __expf(sv[t]-mx); sum += sv[t]; }
    float inv = (j == i) ? 0.f : (1.f/sum);
    #pragma unroll
    for (int t = 0; t < TT; t++) {
        float wv = sv[t]*inv;
        size_t idx = sbase + (size_t)t*NN*NN;
        split2(wv, g_wh + idx, g_wl + idx);
    }
}

// ---------------- kp: P = H @ WQR + brq ; qbr = H @ wqbr + c0 ----------------
__global__ __launch_bounds__(256) void kp_P(const float* __restrict__ H) {
    int bi = blockIdx.x;
    __shared__ float Hs[TT][33];
    __shared__ float Ws[32][DR];
    __shared__ float wqbrs[32];
    int tid = threadIdx.x;
    int t = tid >> 2, rg = (tid & 3)*8;
    float acc[8];
    #pragma unroll
    for (int r = 0; r < 8; r++) acc[r] = 0.f;
    float qacc = 0.f;
    const float* Hbase = H + (size_t)bi*TT*DD;
    for (int d0 = 0; d0 < DD; d0 += 32) {
        #pragma unroll
        for (int l = 0; l < 8; l++) {
            int f = l*256 + tid; int t2 = f >> 5, dd = f & 31;
            Hs[t2][dd] = Hbase[t2*DD + d0 + dd];
        }
        #pragma unroll
        for (int l = 0; l < 4; l++) {
            int f = l*256 + tid; int dd = f >> 5, r = f & 31;
            Ws[dd][r] = g_WQR[(d0 + dd)*DR + r];
        }
        if (tid < 32) wqbrs[tid] = g_wqbr[d0 + tid];
        __syncthreads();
        #pragma unroll
        for (int dd = 0; dd < 32; dd++) {
            float a = Hs[t][dd];
            #pragma unroll
            for (int rr = 0; rr < 8; rr++) acc[rr] += a * Ws[dd][rg + rr];
            qacc += a * wqbrs[dd];
        }
        __syncthreads();
    }
    size_t pb = ((size_t)bi*TT + t)*DR + rg;
    #pragma unroll
    for (int rr = 0; rr < 8; rr++) g_P[pb + rr] = acc[rr] + g_brq[rg + rr];
    if (rg == 0) g_qbr[(size_t)bi*TT + t] = qacc + g_c0;
}

// ---------------- kwr: WR = sum_j w*R, wsum = sum_j w (w = wh+wl) ----------------
__global__ __launch_bounds__(256) void kwr(const float* __restrict__ R) {
    int bi = blockIdx.x; int b = bi >> 8, i = bi & 255;
    __shared__ float Rs[32][33];
    __shared__ float wsm[TT][33];
    int tid = threadIdx.x;
    int t = tid >> 2, rg = (tid & 3)*8;
    float acc[8];
    #pragma unroll
    for (int r = 0; r < 8; r++) acc[r] = 0.f;
    float wsacc = 0.f;
    for (int j0 = 0; j0 < NN; j0 += 32) {
        #pragma unroll
        for (int l = 0; l < 4; l++) {
            int f = l*256 + tid; int jj = f >> 5, r = f & 31;
            Rs[jj][r] = R[((size_t)bi*NN + j0 + jj)*DR + r];
        }
        #pragma unroll
        for (int l = 0; l < 4; l++) {
            int f = l*256 + tid; int t2 = f >> 4, jp = f & 15;
            size_t idx = ((size_t)(b*TT + t2)*NN + i)*NN + j0 + jp*2;
            __nv_bfloat162 hh = *(const __nv_bfloat162*)&g_wh[idx];
            __nv_bfloat162 ll = *(const __nv_bfloat162*)&g_wl[idx];
            wsm[t2][jp*2]     = __low2float(hh)  + __low2float(ll);
            wsm[t2][jp*2 + 1] = __high2float(hh) + __high2float(ll);
        }
        __syncthreads();
        #pragma unroll
        for (int jj = 0; jj < 32; jj++) {
            float wv = wsm[t][jj];
            wsacc += wv;
            #pragma unroll
            for (int rr = 0; rr < 8; rr++) acc[rr] += wv * Rs[jj][rg + rr];
        }
        __syncthreads();
    }
    size_t ob = ((size_t)bi*TT + t)*DR + rg;
    #pragma unroll
    for (int rr = 0; rr < 8; rr++) g_WR[ob + rr] = acc[rr];
    if (rg == 0) g_wsum[(size_t)bi*TT + t] = wsacc;
}

// ---------------- k3m: z2 per (b,t): w @ Bp ----------------
// stage: Ah 10240, Al 10240, Bh 8704, Bl 8704 = 37888; 2 stages = 75776
__global__ __launch_bounds__(256) void k3m() {
    extern __shared__ __align__(128) char dyns[];
    int tid = threadIdx.x, lane = tid & 31, w = tid >> 5;
    int wm = w & 1, wn = w >> 1;
    int bt = blockIdx.z;
    const int m0 = blockIdx.y * 128;
    uint32_t sb = smem_u32p(dyns);
    float acc[4][4][4];
    #pragma unroll
    for (int i = 0; i < 4; i++)
        #pragma unroll
        for (int j = 0; j < 4; j++)
            #pragma unroll
            for (int r = 0; r < 4; r++) acc[i][j][r] = 0.f;
    const uint4* wh4  = (const uint4*)g_wh  + (size_t)bt*NN*32;
    const uint4* wl4  = (const uint4*)g_wl  + (size_t)bt*NN*32;
    const uint4* bph4 = (const uint4*)g_Bph + (size_t)bt*NN*16;
    const uint4* bpl4 = (const uint4*)g_Bpl + (size_t)bt*NN*16;

    auto loadA = [&](uint32_t dst, const uint4* s4, int c) {
        #pragma unroll
        for (int l = 0; l < 2; l++) {
            int f = l*256 + tid; int r = f >> 2, q = f & 3;
            cpa16(dst + (uint32_t)(r*80 + q*16), s4 + (size_t)(m0 + r)*32 + c*4 + q);
        }
    };
    auto loadB = [&](uint32_t dst, const uint4* s4, int c) {
        #pragma unroll
        for (int l = 0; l < 2; l++) {
            int f = l*256 + tid; int r = f >> 4, q = f & 15;
            cpa16(dst + (uint32_t)(r*272 + q*16), s4 + (size_t)(c*32 + r)*16 + q);
        }
    };
    auto prefetch = [&](int stage, int c) {
        uint32_t s0 = sb + stage*37888;
        loadA(s0,         wh4, c);
        loadA(s0 + 10240, wl4, c);
        loadB(s0 + 20480, bph4, c);
        loadB(s0 + 29184, bpl4, c);
        CP_COMMIT();
    };

    prefetch(0, 0);
    #pragma unroll 1
    for (int c = 0; c < 8; c++) {
        int cur = c & 1;
        if (c < 7) { prefetch(cur ^ 1, c + 1); CP_WAIT1(); }
        else       { CP_WAIT0(); }
        __syncthreads();
        uint32_t ahb = sb + cur*37888, alb = ahb + 10240, bhb = ahb + 20480, blb = ahb + 29184;
        #pragma unroll
        for (int ki = 0; ki < 2; ki++) {
            uint32_t ah[4][4], al[4][4], bh[4][2], bl[4][2];
            #pragma unroll
            for (int mf = 0; mf < 4; mf++) {
                uint32_t off = ((wm*64 + mf*16 + (lane & 15))*40 + ki*16 + (lane >> 4)*8)*2;
                ldsm4(ah[mf][0], ah[mf][1], ah[mf][2], ah[mf][3], ahb + off);
                ldsm4(al[mf][0], al[mf][1], al[mf][2], al[mf][3], alb + off);
            }
            #pragma unroll
            for (int g = 0; g < 2; g++) {
                uint32_t off = ((ki*16 + (lane & 15))*136 + wn*32 + g*16 + (lane >> 4)*8)*2;
                uint32_t r0, r1, r2, r3;
                ldsm4t(r0, r1, r2, r3, bhb + off);
                bh[g*2][0] = r0; bh[g*2][1] = r1; bh[g*2+1][0] = r2; bh[g*2+1][1] = r3;
                ldsm4t(r0, r1, r2, r3, blb + off);
                bl[g*2][0] = r0; bl[g*2][1] = r1; bl[g*2+1][0] = r2; bl[g*2+1][1] = r3;
            }
            #pragma unroll
            for (int mf = 0; mf < 4; mf++)
                #pragma unroll
                for (int nf = 0; nf < 4; nf++) {
                    mma16816(acc[mf][nf], ah[mf], bh[nf]);
                    mma16816(acc[mf][nf], al[mf], bh[nf]);
                    mma16816(acc[mf][nf], ah[mf], bl[nf]);
                }
        }
        __syncthreads();
    }
    float* C = g_Z2 + (size_t)bt*NN*DD;
    #pragma unroll
    for (int mf = 0; mf < 4; mf++)
        #pragma unroll
        for (int nf = 0; nf < 4; nf++) {
            int m = m0 + wm*64 + mf*16 + (lane >> 2);
            int n = wn*32 + nf*8 + ((lane & 3) << 1);
            float2 v0 = make_float2(acc[mf][nf][0], acc[mf][nf][1]);
            float2 v1 = make_float2(acc[mf][nf][2], acc[mf][nf][3]);
            *(float2*)&C[(size_t)m*DD + n] = v0;
            *(float2*)&C[(size_t)(m + 8)*DD + n] = v1;
        }
}

// ---------------- kfin: warp-per-row z assembly + residual + LayerNorm ----------------
__global__ __launch_bounds__(256) void kfin(const float* __restrict__ H,
                                            const float* __restrict__ Wf,
                                            const float* __restrict__ bf,
                                            const float* __restrict__ gamma,
                                            const float* __restrict__ beta,
                                            float* __restrict__ out) {
    int bi = blockIdx.x; int b = bi >> 8, i = bi & 255;
    __shared__ float W3s[DD][33];
    __shared__ float WRs[TT][DR];
    __shared__ float wsums[TT];
    __shared__ float bfs[DD], gs[DD], bts[DD];
    int tid = threadIdx.x;
    #pragma unroll
    for (int l = 0; l < 16; l++) {
        int f = l*256 + tid; int e = f >> 5, r = f & 31;
        W3s[e][r] = Wf[e*WF_LD + 2*DD + r];
    }
    #pragma unroll
    for (int l = 0; l < 8; l++) {
        int f = l*256 + tid; int t = f >> 5, r = f & 31;
        WRs[t][r] = g_WR[((size_t)bi*TT + t)*DR + r];
    }
    if (tid < TT) wsums[tid] = g_wsum[(size_t)bi*TT + tid];
    if (tid < DD) { bfs[tid] = bf[tid]; gs[tid] = gamma[tid]; bts[tid] = beta[tid]; }
    __syncthreads();
    int lane = tid & 31, w = tid >> 5;
    #pragma unroll 1
    for (int pass = 0; pass < 8; pass++) {
        int t = pass*8 + w;
        size_t rowH = ((size_t)bi*TT + t)*DD;
        size_t rowZ = ((size_t)(b*TT + t)*NN + i)*DD;
        float wst = wsums[t];
        float z3[4];
        #pragma unroll
        for (int k = 0; k < 4; k++) z3[k] = 0.f;
        #pragma unroll
        for (int r = 0; r < DR; r++) {
            float wr = WRs[t][r];
            #pragma unroll
            for (int k = 0; k < 4; k++) z3[k] += wr * W3s[lane + 32*k][r];
        }
        float v[4], s1 = 0.f, s2 = 0.f;
        #pragma unroll
        for (int k = 0; k < 4; k++) {
            int e = lane + 32*k;
            float x = H[rowH + e] + (g_A[rowH + e] + bfs[e])*wst + g_Z2[rowZ + e] + z3[k];
            v[k] = x; s1 += x; s2 += x*x;
        }
        #pragma unroll
        for (int o = 16; o; o >>= 1) {
            s1 += __shfl_xor_sync(0xffffffffu, s1, o);
            s2 += __shfl_xor_sync(0xffffffffu, s2, o);
        }
        float mu = s1*(1.f/128.f);
        float var = s2*(1.f/128.f) - mu*mu;
        float isd = rsqrtf(var + 1e-5f);
        #pragma unroll
        for (int k = 0; k < 4; k++) {
            int e = lane + 32*k;
            out[rowH + e] = (v[k] - mu)*isd*gs[e] + bts[e];
        }
    }
}

// ---------------- launch ----------------
extern "C" void kernel_launch(void* const* d_in, const int* in_sizes, int n_in,
                              void* d_out, int out_size) {
    const float* H      = (const float*)d_in[0];
    const float* R      = (const float*)d_in[1];
    const float* deltaH = (const float*)d_in[2];
    const float* Wq     = (const float*)d_in[3];
    const float* bq     = (const float*)d_in[4];
    const float* Wk     = (const float*)d_in[5];
    const float* bk     = (const float*)d_in[6];
    const float* Wr     = (const float*)d_in[7];
    const float* br     = (const float*)d_in[8];
    const float* Wf     = (const float*)d_in[9];
    const float* bf     = (const float*)d_in[10];
    const float* gamma  = (const float*)d_in[11];
    const float* beta   = (const float*)d_in[12];
    float* out = (float*)d_out;

    static bool attr_set = false;
    if (!attr_set) {
        cudaFuncSetAttribute(k1m, cudaFuncAttributeMaxDynamicSharedMemorySize, 81920);
        cudaFuncSetAttribute(k2m, cudaFuncAttributeMaxDynamicSharedMemorySize, 81920);
        cudaFuncSetAttribute(k3m, cudaFuncAttributeMaxDynamicSharedMemorySize, 75776);
        attr_set = true;
    }

    kprep<<<1, 128>>>(Wq, bq, Wr, br);
    kw_build<<<256, 256>>>(Wq, Wk, Wf);
    kw4t<<<64, 256>>>(Wf);
    kconv_H<<<8192, 256>>>(H);
    k0a<<<BB*NN, 256>>>(deltaH);
    k0b<<<64, 256>>>();
    k1m<<<dim3(4, 512), 256, 81920>>>(bq, bk);
    kp_P<<<BB*NN, 256>>>(H);
    k2m<<<dim3(2, 2, BB*TT), 256, 81920>>>();
    ksoft<<<BB*NN, 256>>>(R);
    kwr<<<BB*NN, 256>>>(R);
    k3m<<<dim3(1, 2, BB*TT), 256, 75776>>>();
    kfin<<<BB*NN, 256>>>(H, Wf, bf, gamma, beta, out);
}